// round 11
// baseline (speedup 1.0000x reference)
#include <cuda_runtime.h>
#include <cstdint>
#include <cstddef>

#define S_LEN 4096
#define BATCH 8
#define DH    512
#define DIN   2048
#define M_TOT (S_LEN * BATCH)
#define CLUSTER 16
#define RPC   32

__device__ float g_seq[(size_t)M_TOT * DH];
__device__ float g_G[(size_t)M_TOT * 3 * DH];

// ================= GEMM1: seq = x @ Wlm^T (M=32768,N=512,K=2048) ===============
__global__ __launch_bounds__(256) void gemm1_kernel(const float* __restrict__ x,
                                                    const float* __restrict__ Wlm) {
    __shared__ float As[16][132], Bs[16][132];
    const int m0 = blockIdx.y * 128, n0 = blockIdx.x * 128, tid = threadIdx.x;
    const int tx = tid & 15, ty = tid >> 4;
    float acc[8][8] = {};
    for (int k0 = 0; k0 < DIN; k0 += 16) {
#pragma unroll
        for (int i = 0; i < 2; i++) {
            int f = tid * 2 + i, m = f >> 2, kq = f & 3;
            int gm = m0 + m, b = gm & 7, t = gm >> 3;
            float4 v = *reinterpret_cast<const float4*>(x + ((size_t)b * S_LEN + t) * DIN + k0 + kq * 4);
            As[kq*4+0][m] = v.x; As[kq*4+1][m] = v.y; As[kq*4+2][m] = v.z; As[kq*4+3][m] = v.w;
        }
#pragma unroll
        for (int i = 0; i < 2; i++) {
            int f = tid * 2 + i, n = f >> 2, kq = f & 3;
            float4 v = *reinterpret_cast<const float4*>(Wlm + (size_t)(n0 + n) * DIN + k0 + kq * 4);
            Bs[kq*4+0][n] = v.x; Bs[kq*4+1][n] = v.y; Bs[kq*4+2][n] = v.z; Bs[kq*4+3][n] = v.w;
        }
        __syncthreads();
#pragma unroll
        for (int kk = 0; kk < 16; kk++) {
            float4 a0 = *(const float4*)&As[kk][ty*8], a1 = *(const float4*)&As[kk][ty*8+4];
            float4 b0 = *(const float4*)&Bs[kk][tx*4], b1 = *(const float4*)&Bs[kk][64+tx*4];
            float a[8] = {a0.x,a0.y,a0.z,a0.w,a1.x,a1.y,a1.z,a1.w};
            float bb[8] = {b0.x,b0.y,b0.z,b0.w,b1.x,b1.y,b1.z,b1.w};
#pragma unroll
            for (int i = 0; i < 8; i++)
#pragma unroll
                for (int j = 0; j < 8; j++) acc[i][j] = fmaf(a[i], bb[j], acc[i][j]);
        }
        __syncthreads();
    }
#pragma unroll
    for (int i = 0; i < 8; i++) {
        size_t row = (size_t)(m0 + ty * 8 + i) * DH;
        *(float4*)&g_seq[row + n0 + tx*4]      = make_float4(acc[i][0],acc[i][1],acc[i][2],acc[i][3]);
        *(float4*)&g_seq[row + n0 + 64 + tx*4] = make_float4(acc[i][4],acc[i][5],acc[i][6],acc[i][7]);
    }
}

// ============ GEMM2: G = seq @ [Wzx|Wrx|Whx]^T (M=32768,N=1536,K=512) ==========
__global__ __launch_bounds__(256) void gemm2_kernel(const float* __restrict__ Wz,
                                                    const float* __restrict__ Wr,
                                                    const float* __restrict__ Wh) {
    __shared__ float As[16][132], Bs[16][132];
    const int m0 = blockIdx.y * 128, n0 = blockIdx.x * 128, tid = threadIdx.x;
    const int tx = tid & 15, ty = tid >> 4;
    const float* base = (n0 < 512) ? Wz : (n0 < 1024) ? Wr : Wh;
    const int br0 = n0 & 511;
    float acc[8][8] = {};
    for (int k0 = 0; k0 < DH; k0 += 16) {
#pragma unroll
        for (int i = 0; i < 2; i++) {
            int f = tid * 2 + i, m = f >> 2, kq = f & 3;
            float4 v = *reinterpret_cast<const float4*>(g_seq + (size_t)(m0 + m) * DH + k0 + kq * 4);
            As[kq*4+0][m] = v.x; As[kq*4+1][m] = v.y; As[kq*4+2][m] = v.z; As[kq*4+3][m] = v.w;
        }
#pragma unroll
        for (int i = 0; i < 2; i++) {
            int f = tid * 2 + i, n = f >> 2, kq = f & 3;
            float4 v = *reinterpret_cast<const float4*>(base + (size_t)(br0 + n) * 1024 + k0 + kq * 4);
            Bs[kq*4+0][n] = v.x; Bs[kq*4+1][n] = v.y; Bs[kq*4+2][n] = v.z; Bs[kq*4+3][n] = v.w;
        }
        __syncthreads();
#pragma unroll
        for (int kk = 0; kk < 16; kk++) {
            float4 a0 = *(const float4*)&As[kk][ty*8], a1 = *(const float4*)&As[kk][ty*8+4];
            float4 b0 = *(const float4*)&Bs[kk][tx*4], b1 = *(const float4*)&Bs[kk][64+tx*4];
            float a[8] = {a0.x,a0.y,a0.z,a0.w,a1.x,a1.y,a1.z,a1.w};
            float bb[8] = {b0.x,b0.y,b0.z,b0.w,b1.x,b1.y,b1.z,b1.w};
#pragma unroll
            for (int i = 0; i < 8; i++)
#pragma unroll
                for (int j = 0; j < 8; j++) acc[i][j] = fmaf(a[i], bb[j], acc[i][j]);
        }
        __syncthreads();
    }
#pragma unroll
    for (int i = 0; i < 8; i++) {
        size_t row = (size_t)(m0 + ty * 8 + i) * 1536;
        *(float4*)&g_G[row + n0 + tx*4]      = make_float4(acc[i][0],acc[i][1],acc[i][2],acc[i][3]);
        *(float4*)&g_G[row + n0 + 64 + tx*4] = make_float4(acc[i][4],acc[i][5],acc[i][6],acc[i][7]);
    }
}

// ================= helpers =================
__device__ __forceinline__ uint32_t smem_u32(const void* p) {
    return (uint32_t)__cvta_generic_to_shared(p);
}
__device__ __forceinline__ uint32_t dsmem_map(uint32_t a, unsigned r) {
    uint32_t x; asm("mapa.shared::cluster.u32 %0, %1, %2;" : "=r"(x) : "r"(a), "r"(r)); return x;
}
__device__ __forceinline__ void st_async64(uint32_t a, uint32_t mbar, float x, float y) {
    unsigned long long v = ((unsigned long long)__float_as_uint(y) << 32) | __float_as_uint(x);
    asm volatile("st.async.shared::cluster.mbarrier::complete_tx::bytes.u64 [%0], %1, [%2];"
                 :: "r"(a), "l"(v), "r"(mbar) : "memory");
}
__device__ __forceinline__ void mbar_init(uint32_t a, uint32_t cnt) {
    asm volatile("mbarrier.init.shared.b64 [%0], %1;" :: "r"(a), "r"(cnt) : "memory");
}
__device__ __forceinline__ void mbar_expect_tx(uint32_t a, uint32_t tx) {
    asm volatile("mbarrier.arrive.expect_tx.shared.b64 _, [%0], %1;" :: "r"(a), "r"(tx) : "memory");
}
__device__ __forceinline__ void mbar_wait(uint32_t a, uint32_t parity) {
    uint32_t done;
    asm volatile("{\n\t.reg .pred p;\n\t"
                 "mbarrier.try_wait.parity.shared.b64 p, [%1], %2;\n\t"
                 "selp.b32 %0, 1, 0, p;\n\t}"
                 : "=r"(done) : "r"(a), "r"(parity) : "memory");
    while (!done) {
        asm volatile("{\n\t.reg .pred p;\n\t"
                     "mbarrier.try_wait.parity.shared.b64 p, [%1], %2;\n\t"
                     "selp.b32 %0, 1, 0, p;\n\t}"
                     : "=r"(done) : "r"(a), "r"(parity) : "memory");
    }
}
__device__ __forceinline__ void cl_sync() {
    asm volatile("barrier.cluster.arrive.aligned;" ::: "memory");
    asm volatile("barrier.cluster.wait.aligned;"   ::: "memory");
}
__device__ __forceinline__ float sigmoidf_(float v) { return 1.f / (1.f + __expf(-v)); }
__device__ __forceinline__ float tanh_fast(float v) {
    float y; asm("tanh.approx.f32 %0, %1;" : "=f"(y) : "f"(v)); return y;
}

// == GRU: 8 clusters x 16 CTAs x 512 thr; symmetric warps, z in registers =======
// Warp w owns local rows {2w, 2w+1} for ALL gates: r -> push r*h -> z (regs, in
// fabric shadow) -> wait rh -> h' -> h-update (z from regs) -> push h -> wait h.
__global__ void __cluster_dims__(CLUSTER, 1, 1) __launch_bounds__(512, 1)
gru_kernel(const float* __restrict__ Wz, const float* __restrict__ Wr,
           const float* __restrict__ Wh, const float* __restrict__ Wc,
           float* __restrict__ out) {
    extern __shared__ float sm[];
    float* wAll = sm;                    // [96][512]: r 0-31, z 32-63, h 64-95
    float* hbuf = sm + 96 * 512;         // [2][512]
    float* rhbf = hbuf + 1024;           // [2][512]
    uint32_t mb_rh = smem_u32(rhbf + 1024);  // 8B each
    uint32_t mb_h  = mb_rh + 8;

    const int tid = threadIdx.x;
    unsigned rank; asm("mov.u32 %0, %%cluster_ctarank;" : "=r"(rank));
    const int b  = blockIdx.x / CLUSTER;
    const int j0 = (int)rank * RPC;
    const int w = tid >> 5, l = tid & 31;

    for (int i = tid; i < 32 * 128; i += 512) {
        int r = i >> 7, q = (i & 127) * 4;
        *(float4*)&wAll[r * 512 + q]        = *(const float4*)(Wr + (size_t)(j0 + r) * 1024 + 512 + q);
        *(float4*)&wAll[(32 + r) * 512 + q] = *(const float4*)(Wz + (size_t)(j0 + r) * 1024 + 512 + q);
        *(float4*)&wAll[(64 + r) * 512 + q] = *(const float4*)(Wh + (size_t)(j0 + r) * 1024 + 512 + q);
    }
    for (int i = tid; i < 1024; i += 512) hbuf[i] = 0.f;
    if (tid == 0) { mbar_init(mb_rh, 1); mbar_init(mb_h, 1); }
    __syncthreads();

    const int r0 = 2 * w;                          // this warp's 2 local rows
    // push endpoints: lane l<16 pushes the warp's 2 rows (8B) to rank l
    uint32_t rh_d0 = 0, rh_d1 = 0, h_d0 = 0, h_d1 = 0, mrh_r = 0, mh_r = 0;
    if (l < 16) {
        rh_d0 = dsmem_map(smem_u32(&rhbf[0 * 512 + j0 + r0]), (unsigned)l);
        rh_d1 = dsmem_map(smem_u32(&rhbf[1 * 512 + j0 + r0]), (unsigned)l);
        h_d0  = dsmem_map(smem_u32(&hbuf[0 * 512 + j0 + r0]), (unsigned)l);
        h_d1  = dsmem_map(smem_u32(&hbuf[1 * 512 + j0 + r0]), (unsigned)l);
        mrh_r = dsmem_map(mb_rh, (unsigned)l);
        mh_r  = dsmem_map(mb_h, (unsigned)l);
    }
    const size_t gz_o = j0 + r0, gr_o = 512 + j0 + r0, gh_o = 1024 + j0 + r0;

    cl_sync();                                     // mbars + h0 + weights live

    float2 gr = *(const float2*)(g_G + (size_t)b * 1536 + gr_o);
    float2 gz = *(const float2*)(g_G + (size_t)b * 1536 + gz_o);
    float2 gh = *(const float2*)(g_G + (size_t)b * 1536 + gh_o);

    int p = 0;
    uint32_t ph = 0;
    for (int t = 0; t < S_LEN; t++) {
        if (tid == 0) {                            // arm tx budgets (256 x 8B)
            mbar_expect_tx(mb_rh, 2048);
            mbar_expect_tx(mb_h, 2048);
        }
        const int tn = (t + 1 < S_LEN) ? t + 1 : t;
        const size_t gbn = ((size_t)tn * 8 + b) * 1536;
        const int rb = t & 1;

        // ---- load h once, reused by r and z gates ----
        float4 h4[4];
#pragma unroll
        for (int q = 0; q < 4; q++) h4[q] = *(const float4*)&hbuf[p * 512 + q * 128 + l * 4];
        float2 ho = *(const float2*)&hbuf[p * 512 + j0 + r0];

        // ---- r gate (2 rows) ----
        float a0 = 0.f, a1 = 0.f;
#pragma unroll
        for (int q = 0; q < 4; q++) {
            float4 w0 = *(const float4*)&wAll[r0 * 512 + q * 128 + l * 4];
            float4 w1 = *(const float4*)&wAll[(r0 + 1) * 512 + q * 128 + l * 4];
            a0 = fmaf(w0.x, h4[q].x, a0); a0 = fmaf(w0.y, h4[q].y, a0);
            a0 = fmaf(w0.z, h4[q].z, a0); a0 = fmaf(w0.w, h4[q].w, a0);
            a1 = fmaf(w1.x, h4[q].x, a1); a1 = fmaf(w1.y, h4[q].y, a1);
            a1 = fmaf(w1.z, h4[q].z, a1); a1 = fmaf(w1.w, h4[q].w, a1);
        }
#pragma unroll
        for (int d = 16; d; d >>= 1) {
            a0 += __shfl_xor_sync(~0u, a0, d);
            a1 += __shfl_xor_sync(~0u, a1, d);
        }
        if (l < 16) {
            float rh0 = sigmoidf_(a0 + gr.x) * ho.x;
            float rh1 = sigmoidf_(a1 + gr.y) * ho.y;
            st_async64(rb ? rh_d1 : rh_d0, mrh_r, rh0, rh1);
        }

        // ---- z gate (2 rows) in the fabric shadow; stays in registers ----
        float b0 = 0.f, b1 = 0.f;
#pragma unroll
        for (int q = 0; q < 4; q++) {
            float4 w0 = *(const float4*)&wAll[(32 + r0) * 512 + q * 128 + l * 4];
            float4 w1 = *(const float4*)&wAll[(33 + r0) * 512 + q * 128 + l * 4];
            b0 = fmaf(w0.x, h4[q].x, b0); b0 = fmaf(w0.y, h4[q].y, b0);
            b0 = fmaf(w0.z, h4[q].z, b0); b0 = fmaf(w0.w, h4[q].w, b0);
            b1 = fmaf(w1.x, h4[q].x, b1); b1 = fmaf(w1.y, h4[q].y, b1);
            b1 = fmaf(w1.z, h4[q].z, b1); b1 = fmaf(w1.w, h4[q].w, b1);
        }
#pragma unroll
        for (int d = 16; d; d >>= 1) {
            b0 += __shfl_xor_sync(~0u, b0, d);
            b1 += __shfl_xor_sync(~0u, b1, d);
        }
        const float z0 = sigmoidf_(b0 + gz.x);
        const float z1 = sigmoidf_(b1 + gz.y);

        // prefetch next step's gate-x pre-acts (off critical path)
        float2 gnr = *(const float2*)(g_G + gbn + gr_o);
        float2 gnz = *(const float2*)(g_G + gbn + gz_o);
        float2 gnh = *(const float2*)(g_G + gbn + gh_o);

        mbar_wait(mb_rh, ph);                      // full r*h resident locally

        // ---- h' gate (2 rows) over r*h ----
        float4 r4[4];
#pragma unroll
        for (int q = 0; q < 4; q++) r4[q] = *(const float4*)&rhbf[rb * 512 + q * 128 + l * 4];
        float c0 = 0.f, c1 = 0.f;
#pragma unroll
        for (int q = 0; q < 4; q++) {
            float4 w0 = *(const float4*)&wAll[(64 + r0) * 512 + q * 128 + l * 4];
            float4 w1 = *(const float4*)&wAll[(65 + r0) * 512 + q * 128 + l * 4];
            c0 = fmaf(w0.x, r4[q].x, c0); c0 = fmaf(w0.y, r4[q].y, c0);
            c0 = fmaf(w0.z, r4[q].z, c0); c0 = fmaf(w0.w, r4[q].w, c0);
            c1 = fmaf(w1.x, r4[q].x, c1); c1 = fmaf(w1.y, r4[q].y, c1);
            c1 = fmaf(w1.z, r4[q].z, c1); c1 = fmaf(w1.w, r4[q].w, c1);
        }
#pragma unroll
        for (int d = 16; d; d >>= 1) {
            c0 += __shfl_xor_sync(~0u, c0, d);
            c1 += __shfl_xor_sync(~0u, c1, d);
        }
        if (l < 16) {
            float hc0 = tanh_fast(c0 + gh.x);
            float hc1 = tanh_fast(c1 + gh.y);
            float hn0 = ho.x + z0 * (hc0 - ho.x);
            float hn1 = ho.y + z1 * (hc1 - ho.y);
            st_async64(p ? h_d0 : h_d1, mh_r, hn0, hn1);   // -> hbuf[p^1]
        }
        mbar_wait(mb_h, ph);                       // h(t+1) resident locally

        gr = gnr; gz = gnz; gh = gnh;
        ph ^= 1; p ^= 1;
    }

    // classifier: final h in hbuf[0]; rank 0 writes out[b][10]
    if (rank == 0 && w < 10) {
        float s = 0.f;
        for (int k = l; k < DH; k += 32)
            s += hbuf[k] * Wc[(size_t)w * DH + k];
#pragma unroll
        for (int d = 16; d; d >>= 1) s += __shfl_xor_sync(~0u, s, d);
        if (l == 0) out[b * 10 + w] = s;
    }
    cl_sync();                                     // no early-exit vs peer DSMEM
}

extern "C" void kernel_launch(void* const* d_in, const int* in_sizes, int n_in,
                              void* d_out, int out_size) {
    const float* x   = (const float*)d_in[0];
    const float* Wlm = (const float*)d_in[1];
    const float* Wz  = (const float*)d_in[2];
    const float* Wr  = (const float*)d_in[3];
    const float* Wh  = (const float*)d_in[4];
    const float* Wc  = (const float*)d_in[5];
    float* out = (float*)d_out;

    const int smem_bytes = (96 * 512 + 1024 + 1024) * 4 + 16;
    cudaFuncSetAttribute(gru_kernel, cudaFuncAttributeNonPortableClusterSizeAllowed, 1);
    cudaFuncSetAttribute(gru_kernel, cudaFuncAttributeMaxDynamicSharedMemorySize, smem_bytes);

    gemm1_kernel<<<dim3(4, 256), 256>>>(x, Wlm);
    gemm2_kernel<<<dim3(12, 256), 256>>>(Wz, Wr, Wh);
    gru_kernel<<<BATCH * CLUSTER, 512, smem_bytes>>>(Wz, Wr, Wh, Wc, out);
}

// round 12
// speedup vs baseline: 1.1209x; 1.1209x over previous
#include <cuda_runtime.h>
#include <cstdint>
#include <cstddef>

#define S_LEN 4096
#define BATCH 8
#define DH    512
#define DIN   2048
#define M_TOT (S_LEN * BATCH)
#define CLUSTER 16
#define RPC   32

__device__ float g_seq[(size_t)M_TOT * DH];
__device__ float g_G[(size_t)M_TOT * 3 * DH];

// ================= GEMM1: seq = x @ Wlm^T (M=32768,N=512,K=2048) ===============
__global__ __launch_bounds__(256) void gemm1_kernel(const float* __restrict__ x,
                                                    const float* __restrict__ Wlm) {
    __shared__ float As[16][132], Bs[16][132];
    const int m0 = blockIdx.y * 128, n0 = blockIdx.x * 128, tid = threadIdx.x;
    const int tx = tid & 15, ty = tid >> 4;
    float acc[8][8] = {};
    for (int k0 = 0; k0 < DIN; k0 += 16) {
#pragma unroll
        for (int i = 0; i < 2; i++) {
            int f = tid * 2 + i, m = f >> 2, kq = f & 3;
            int gm = m0 + m, b = gm & 7, t = gm >> 3;
            float4 v = *reinterpret_cast<const float4*>(x + ((size_t)b * S_LEN + t) * DIN + k0 + kq * 4);
            As[kq*4+0][m] = v.x; As[kq*4+1][m] = v.y; As[kq*4+2][m] = v.z; As[kq*4+3][m] = v.w;
        }
#pragma unroll
        for (int i = 0; i < 2; i++) {
            int f = tid * 2 + i, n = f >> 2, kq = f & 3;
            float4 v = *reinterpret_cast<const float4*>(Wlm + (size_t)(n0 + n) * DIN + k0 + kq * 4);
            Bs[kq*4+0][n] = v.x; Bs[kq*4+1][n] = v.y; Bs[kq*4+2][n] = v.z; Bs[kq*4+3][n] = v.w;
        }
        __syncthreads();
#pragma unroll
        for (int kk = 0; kk < 16; kk++) {
            float4 a0 = *(const float4*)&As[kk][ty*8], a1 = *(const float4*)&As[kk][ty*8+4];
            float4 b0 = *(const float4*)&Bs[kk][tx*4], b1 = *(const float4*)&Bs[kk][64+tx*4];
            float a[8] = {a0.x,a0.y,a0.z,a0.w,a1.x,a1.y,a1.z,a1.w};
            float bb[8] = {b0.x,b0.y,b0.z,b0.w,b1.x,b1.y,b1.z,b1.w};
#pragma unroll
            for (int i = 0; i < 8; i++)
#pragma unroll
                for (int j = 0; j < 8; j++) acc[i][j] = fmaf(a[i], bb[j], acc[i][j]);
        }
        __syncthreads();
    }
#pragma unroll
    for (int i = 0; i < 8; i++) {
        size_t row = (size_t)(m0 + ty * 8 + i) * DH;
        *(float4*)&g_seq[row + n0 + tx*4]      = make_float4(acc[i][0],acc[i][1],acc[i][2],acc[i][3]);
        *(float4*)&g_seq[row + n0 + 64 + tx*4] = make_float4(acc[i][4],acc[i][5],acc[i][6],acc[i][7]);
    }
}

// ============ GEMM2: G = seq @ [Wzx|Wrx|Whx]^T (M=32768,N=1536,K=512) ==========
__global__ __launch_bounds__(256) void gemm2_kernel(const float* __restrict__ Wz,
                                                    const float* __restrict__ Wr,
                                                    const float* __restrict__ Wh) {
    __shared__ float As[16][132], Bs[16][132];
    const int m0 = blockIdx.y * 128, n0 = blockIdx.x * 128, tid = threadIdx.x;
    const int tx = tid & 15, ty = tid >> 4;
    const float* base = (n0 < 512) ? Wz : (n0 < 1024) ? Wr : Wh;
    const int br0 = n0 & 511;
    float acc[8][8] = {};
    for (int k0 = 0; k0 < DH; k0 += 16) {
#pragma unroll
        for (int i = 0; i < 2; i++) {
            int f = tid * 2 + i, m = f >> 2, kq = f & 3;
            float4 v = *reinterpret_cast<const float4*>(g_seq + (size_t)(m0 + m) * DH + k0 + kq * 4);
            As[kq*4+0][m] = v.x; As[kq*4+1][m] = v.y; As[kq*4+2][m] = v.z; As[kq*4+3][m] = v.w;
        }
#pragma unroll
        for (int i = 0; i < 2; i++) {
            int f = tid * 2 + i, n = f >> 2, kq = f & 3;
            float4 v = *reinterpret_cast<const float4*>(base + (size_t)(br0 + n) * 1024 + k0 + kq * 4);
            Bs[kq*4+0][n] = v.x; Bs[kq*4+1][n] = v.y; Bs[kq*4+2][n] = v.z; Bs[kq*4+3][n] = v.w;
        }
        __syncthreads();
#pragma unroll
        for (int kk = 0; kk < 16; kk++) {
            float4 a0 = *(const float4*)&As[kk][ty*8], a1 = *(const float4*)&As[kk][ty*8+4];
            float4 b0 = *(const float4*)&Bs[kk][tx*4], b1 = *(const float4*)&Bs[kk][64+tx*4];
            float a[8] = {a0.x,a0.y,a0.z,a0.w,a1.x,a1.y,a1.z,a1.w};
            float bb[8] = {b0.x,b0.y,b0.z,b0.w,b1.x,b1.y,b1.z,b1.w};
#pragma unroll
            for (int i = 0; i < 8; i++)
#pragma unroll
                for (int j = 0; j < 8; j++) acc[i][j] = fmaf(a[i], bb[j], acc[i][j]);
        }
        __syncthreads();
    }
#pragma unroll
    for (int i = 0; i < 8; i++) {
        size_t row = (size_t)(m0 + ty * 8 + i) * 1536;
        *(float4*)&g_G[row + n0 + tx*4]      = make_float4(acc[i][0],acc[i][1],acc[i][2],acc[i][3]);
        *(float4*)&g_G[row + n0 + 64 + tx*4] = make_float4(acc[i][4],acc[i][5],acc[i][6],acc[i][7]);
    }
}

// ================= helpers =================
__device__ __forceinline__ uint32_t smem_u32(const void* p) {
    return (uint32_t)__cvta_generic_to_shared(p);
}
__device__ __forceinline__ uint32_t dsmem_map(uint32_t a, unsigned r) {
    uint32_t x; asm("mapa.shared::cluster.u32 %0, %1, %2;" : "=r"(x) : "r"(a), "r"(r)); return x;
}
__device__ __forceinline__ void st_async64(uint32_t a, uint32_t mbar, float x, float y) {
    unsigned long long v = ((unsigned long long)__float_as_uint(y) << 32) | __float_as_uint(x);
    asm volatile("st.async.shared::cluster.mbarrier::complete_tx::bytes.u64 [%0], %1, [%2];"
                 :: "r"(a), "l"(v), "r"(mbar) : "memory");
}
__device__ __forceinline__ void mbar_init(uint32_t a, uint32_t cnt) {
    asm volatile("mbarrier.init.shared.b64 [%0], %1;" :: "r"(a), "r"(cnt) : "memory");
}
__device__ __forceinline__ void mbar_expect_tx(uint32_t a, uint32_t tx) {
    asm volatile("mbarrier.arrive.expect_tx.shared.b64 _, [%0], %1;" :: "r"(a), "r"(tx) : "memory");
}
__device__ __forceinline__ void mbar_wait(uint32_t a, uint32_t parity) {
    uint32_t done;
    asm volatile("{\n\t.reg .pred p;\n\t"
                 "mbarrier.try_wait.parity.shared.b64 p, [%1], %2, 0x989680;\n\t"
                 "selp.b32 %0, 1, 0, p;\n\t}"
                 : "=r"(done) : "r"(a), "r"(parity) : "memory");
    while (!done) {
        asm volatile("{\n\t.reg .pred p;\n\t"
                     "mbarrier.try_wait.parity.shared.b64 p, [%1], %2, 0x989680;\n\t"
                     "selp.b32 %0, 1, 0, p;\n\t}"
                     : "=r"(done) : "r"(a), "r"(parity) : "memory");
    }
}
__device__ __forceinline__ void cl_sync() {
    asm volatile("barrier.cluster.arrive.aligned;" ::: "memory");
    asm volatile("barrier.cluster.wait.aligned;"   ::: "memory");
}
__device__ __forceinline__ float sigmoidf_(float v) { return 1.f / (1.f + __expf(-v)); }
__device__ __forceinline__ float tanh_fast(float v) {
    float y; asm("tanh.approx.f32 %0, %1;" : "=f"(y) : "f"(v)); return y;
}

// dot of 2 weight rows against the warp-distributed vector v4, full warp reduce
__device__ __forceinline__ void dot2(const float* wr0, const float* wr1,
                                     const float4* v4, int l, float& s0, float& s1) {
    float a0 = 0.f, a1 = 0.f;
#pragma unroll
    for (int q = 0; q < 4; q++) {
        float4 w0 = *(const float4*)(wr0 + q * 128 + l * 4);
        float4 w1 = *(const float4*)(wr1 + q * 128 + l * 4);
        a0 = fmaf(w0.x, v4[q].x, a0); a0 = fmaf(w0.y, v4[q].y, a0);
        a0 = fmaf(w0.z, v4[q].z, a0); a0 = fmaf(w0.w, v4[q].w, a0);
        a1 = fmaf(w1.x, v4[q].x, a1); a1 = fmaf(w1.y, v4[q].y, a1);
        a1 = fmaf(w1.z, v4[q].z, a1); a1 = fmaf(w1.w, v4[q].w, a1);
    }
#pragma unroll
    for (int d = 16; d; d >>= 1) {
        a0 += __shfl_xor_sync(~0u, a0, d);
        a1 += __shfl_xor_sync(~0u, a1, d);
    }
    s0 = a0; s1 = a1;
}

// == GRU: 4 clusters x 16 CTAs x 512 thr; 2 batches/cluster, pipelined exchange =
__global__ void __cluster_dims__(CLUSTER, 1, 1) __launch_bounds__(512, 1)
gru_kernel(const float* __restrict__ Wz, const float* __restrict__ Wr,
           const float* __restrict__ Wh, const float* __restrict__ Wc,
           float* __restrict__ out) {
    extern __shared__ float sm[];
    float* wAll  = sm;                   // [96][512]: r 0-31, z 32-63, h 64-95
    float* hb[2]  = { sm + 96 * 512,           sm + 96 * 512 + 1024 };  // [2][512] each
    float* rb_[2] = { sm + 96 * 512 + 2048,    sm + 96 * 512 + 3072 };  // [2][512] each
    uint32_t mbb = smem_u32(sm + 96 * 512 + 4096);
    // per-batch barriers: mb_rh[B], mb_h[B]
    uint32_t mb_rh[2] = { mbb, mbb + 8 };
    uint32_t mb_h[2]  = { mbb + 16, mbb + 24 };

    const int tid = threadIdx.x;
    unsigned rank; asm("mov.u32 %0, %%cluster_ctarank;" : "=r"(rank));
    const int b0 = 2 * (blockIdx.x / CLUSTER);     // this cluster's 2 batches
    const int j0 = (int)rank * RPC;
    const int w = tid >> 5, l = tid & 31;

    for (int i = tid; i < 32 * 128; i += 512) {
        int r = i >> 7, q = (i & 127) * 4;
        *(float4*)&wAll[r * 512 + q]        = *(const float4*)(Wr + (size_t)(j0 + r) * 1024 + 512 + q);
        *(float4*)&wAll[(32 + r) * 512 + q] = *(const float4*)(Wz + (size_t)(j0 + r) * 1024 + 512 + q);
        *(float4*)&wAll[(64 + r) * 512 + q] = *(const float4*)(Wh + (size_t)(j0 + r) * 1024 + 512 + q);
    }
    for (int i = tid; i < 2048; i += 512) { hb[0][i & 1023] = 0.f; hb[i >> 10][i & 1023] = 0.f; }
    for (int i = tid; i < 1024; i += 512) { hb[0][i] = 0.f; hb[1][i] = 0.f; }
    if (tid == 0)
#pragma unroll
        for (int B = 0; B < 2; B++) { mbar_init(mb_rh[B], 1); mbar_init(mb_h[B], 1); }
    __syncthreads();

    const int r0 = 2 * w;                          // this warp's 2 local rows
    // push endpoints per batch: lane l<16 pushes the warp's 2 rows (8B) to rank l
    uint32_t rh_d[2][2], h_d[2][2], mrh_r[2], mh_r[2];
    if (l < 16) {
#pragma unroll
        for (int B = 0; B < 2; B++) {
            rh_d[B][0] = dsmem_map(smem_u32(&rb_[B][0 * 512 + j0 + r0]), (unsigned)l);
            rh_d[B][1] = dsmem_map(smem_u32(&rb_[B][1 * 512 + j0 + r0]), (unsigned)l);
            h_d[B][0]  = dsmem_map(smem_u32(&hb[B][0 * 512 + j0 + r0]), (unsigned)l);
            h_d[B][1]  = dsmem_map(smem_u32(&hb[B][1 * 512 + j0 + r0]), (unsigned)l);
            mrh_r[B] = dsmem_map(mb_rh[B], (unsigned)l);
            mh_r[B]  = dsmem_map(mb_h[B], (unsigned)l);
        }
    }
    const size_t gz_o = j0 + r0, gr_o = 512 + j0 + r0, gh_o = 1024 + j0 + r0;

    cl_sync();                                     // mbars + h0 + weights live

    float2 gr[2], gz[2], gh[2];
#pragma unroll
    for (int B = 0; B < 2; B++) {
        const size_t gb = (size_t)(b0 + B) * 1536;
        gr[B] = *(const float2*)(g_G + gb + gr_o);
        gz[B] = *(const float2*)(g_G + gb + gz_o);
        gh[B] = *(const float2*)(g_G + gb + gh_o);
    }

    int p = 0;
    uint32_t ph = 0;
    for (int t = 0; t < S_LEN; t++) {
        if (tid == 0) {
#pragma unroll
            for (int B = 0; B < 2; B++) {
                mbar_expect_tx(mb_rh[B], 2048);
                mbar_expect_tx(mb_h[B], 2048);
            }
        }
        const int tn = (t + 1 < S_LEN) ? t + 1 : t;
        const int rbix = t & 1;

        // ---- phase A: r gates for both batches (push early), then z gates ----
        float4 h4[2][4];
        float2 ho[2];
        float z0[2], z1[2];
#pragma unroll
        for (int B = 0; B < 2; B++) {
#pragma unroll
            for (int q = 0; q < 4; q++)
                h4[B][q] = *(const float4*)&hb[B][p * 512 + q * 128 + l * 4];
            ho[B] = *(const float2*)&hb[B][p * 512 + j0 + r0];
            float s0, s1;
            dot2(&wAll[r0 * 512], &wAll[(r0 + 1) * 512], h4[B], l, s0, s1);
            if (l < 16) {
                float rh0 = sigmoidf_(s0 + gr[B].x) * ho[B].x;
                float rh1 = sigmoidf_(s1 + gr[B].y) * ho[B].y;
                st_async64(rh_d[B][rbix], mrh_r[B], rh0, rh1);
            }
        }
#pragma unroll
        for (int B = 0; B < 2; B++) {
            float s0, s1;
            dot2(&wAll[(32 + r0) * 512], &wAll[(33 + r0) * 512], h4[B], l, s0, s1);
            z0[B] = sigmoidf_(s0 + gz[B].x);
            z1[B] = sigmoidf_(s1 + gz[B].y);
        }

        // prefetch next step's gate-x pre-acts (off critical path)
        float2 gnr[2], gnz[2], gnh[2];
#pragma unroll
        for (int B = 0; B < 2; B++) {
            const size_t gbn = ((size_t)tn * 8 + b0 + B) * 1536;
            gnr[B] = *(const float2*)(g_G + gbn + gr_o);
            gnz[B] = *(const float2*)(g_G + gbn + gz_o);
            gnh[B] = *(const float2*)(g_G + gbn + gh_o);
        }

        // ---- phase B: h' per batch as its r*h arrives; push h ----
#pragma unroll
        for (int B = 0; B < 2; B++) {
            mbar_wait(mb_rh[B], ph);
            float4 r4[4];
#pragma unroll
            for (int q = 0; q < 4; q++)
                r4[q] = *(const float4*)&rb_[B][rbix * 512 + q * 128 + l * 4];
            float s0, s1;
            dot2(&wAll[(64 + r0) * 512], &wAll[(65 + r0) * 512], r4, l, s0, s1);
            if (l < 16) {
                float hc0 = tanh_fast(s0 + gh[B].x);
                float hc1 = tanh_fast(s1 + gh[B].y);
                float hn0 = ho[B].x + z0[B] * (hc0 - ho[B].x);
                float hn1 = ho[B].y + z1[B] * (hc1 - ho[B].y);
                st_async64(h_d[B][p ^ 1], mh_r[B], hn0, hn1);
            }
        }
        mbar_wait(mb_h[0], ph);
        mbar_wait(mb_h[1], ph);

#pragma unroll
        for (int B = 0; B < 2; B++) { gr[B] = gnr[B]; gz[B] = gnz[B]; gh[B] = gnh[B]; }
        ph ^= 1; p ^= 1;
    }

    // classifier: final h in hb[B][0]; rank 0 writes out[b0+B][10]
    if (rank == 0 && w < 10) {
#pragma unroll
        for (int B = 0; B < 2; B++) {
            float s = 0.f;
            for (int k = l; k < DH; k += 32)
                s += hb[B][k] * Wc[(size_t)w * DH + k];
#pragma unroll
            for (int d = 16; d; d >>= 1) s += __shfl_xor_sync(~0u, s, d);
            if (l == 0) out[(b0 + B) * 10 + w] = s;
        }
    }
    cl_sync();                                     // no early-exit vs peer DSMEM
}

extern "C" void kernel_launch(void* const* d_in, const int* in_sizes, int n_in,
                              void* d_out, int out_size) {
    const float* x   = (const float*)d_in[0];
    const float* Wlm = (const float*)d_in[1];
    const float* Wz  = (const float*)d_in[2];
    const float* Wr  = (const float*)d_in[3];
    const float* Wh  = (const float*)d_in[4];
    const float* Wc  = (const float*)d_in[5];
    float* out = (float*)d_out;

    const int smem_bytes = (96 * 512 + 4 * 1024) * 4 + 32;
    cudaFuncSetAttribute(gru_kernel, cudaFuncAttributeNonPortableClusterSizeAllowed, 1);
    cudaFuncSetAttribute(gru_kernel, cudaFuncAttributeMaxDynamicSharedMemorySize, smem_bytes);

    gemm1_kernel<<<dim3(4, 256), 256>>>(x, Wlm);
    gemm2_kernel<<<dim3(12, 256), 256>>>(Wz, Wr, Wh);
    gru_kernel<<<(BATCH / 2) * CLUSTER, 512, smem_bytes>>>(Wz, Wr, Wh, Wc, out);
}

// round 13
// speedup vs baseline: 1.2462x; 1.1118x over previous
#include <cuda_runtime.h>
#include <cstdint>
#include <cstddef>

#define S_LEN 4096
#define BATCH 8
#define DH    512
#define DIN   2048
#define M_TOT (S_LEN * BATCH)
#define CLUSTER 16
#define RPC   32

__device__ float g_seq[(size_t)M_TOT * DH];
__device__ float g_G[(size_t)M_TOT * 3 * DH];

// ================= GEMM1: seq = x @ Wlm^T (M=32768,N=512,K=2048) ===============
__global__ __launch_bounds__(256) void gemm1_kernel(const float* __restrict__ x,
                                                    const float* __restrict__ Wlm) {
    __shared__ float As[16][132], Bs[16][132];
    const int m0 = blockIdx.y * 128, n0 = blockIdx.x * 128, tid = threadIdx.x;
    const int tx = tid & 15, ty = tid >> 4;
    float acc[8][8] = {};
    for (int k0 = 0; k0 < DIN; k0 += 16) {
#pragma unroll
        for (int i = 0; i < 2; i++) {
            int f = tid * 2 + i, m = f >> 2, kq = f & 3;
            int gm = m0 + m, b = gm & 7, t = gm >> 3;
            float4 v = *reinterpret_cast<const float4*>(x + ((size_t)b * S_LEN + t) * DIN + k0 + kq * 4);
            As[kq*4+0][m] = v.x; As[kq*4+1][m] = v.y; As[kq*4+2][m] = v.z; As[kq*4+3][m] = v.w;
        }
#pragma unroll
        for (int i = 0; i < 2; i++) {
            int f = tid * 2 + i, n = f >> 2, kq = f & 3;
            float4 v = *reinterpret_cast<const float4*>(Wlm + (size_t)(n0 + n) * DIN + k0 + kq * 4);
            Bs[kq*4+0][n] = v.x; Bs[kq*4+1][n] = v.y; Bs[kq*4+2][n] = v.z; Bs[kq*4+3][n] = v.w;
        }
        __syncthreads();
#pragma unroll
        for (int kk = 0; kk < 16; kk++) {
            float4 a0 = *(const float4*)&As[kk][ty*8], a1 = *(const float4*)&As[kk][ty*8+4];
            float4 b0 = *(const float4*)&Bs[kk][tx*4], b1 = *(const float4*)&Bs[kk][64+tx*4];
            float a[8] = {a0.x,a0.y,a0.z,a0.w,a1.x,a1.y,a1.z,a1.w};
            float bb[8] = {b0.x,b0.y,b0.z,b0.w,b1.x,b1.y,b1.z,b1.w};
#pragma unroll
            for (int i = 0; i < 8; i++)
#pragma unroll
                for (int j = 0; j < 8; j++) acc[i][j] = fmaf(a[i], bb[j], acc[i][j]);
        }
        __syncthreads();
    }
#pragma unroll
    for (int i = 0; i < 8; i++) {
        size_t row = (size_t)(m0 + ty * 8 + i) * DH;
        *(float4*)&g_seq[row + n0 + tx*4]      = make_float4(acc[i][0],acc[i][1],acc[i][2],acc[i][3]);
        *(float4*)&g_seq[row + n0 + 64 + tx*4] = make_float4(acc[i][4],acc[i][5],acc[i][6],acc[i][7]);
    }
}

// ============ GEMM2: G = seq @ [Wzx|Wrx|Whx]^T (M=32768,N=1536,K=512) ==========
__global__ __launch_bounds__(256) void gemm2_kernel(const float* __restrict__ Wz,
                                                    const float* __restrict__ Wr,
                                                    const float* __restrict__ Wh) {
    __shared__ float As[16][132], Bs[16][132];
    const int m0 = blockIdx.y * 128, n0 = blockIdx.x * 128, tid = threadIdx.x;
    const int tx = tid & 15, ty = tid >> 4;
    const float* base = (n0 < 512) ? Wz : (n0 < 1024) ? Wr : Wh;
    const int br0 = n0 & 511;
    float acc[8][8] = {};
    for (int k0 = 0; k0 < DH; k0 += 16) {
#pragma unroll
        for (int i = 0; i < 2; i++) {
            int f = tid * 2 + i, m = f >> 2, kq = f & 3;
            float4 v = *reinterpret_cast<const float4*>(g_seq + (size_t)(m0 + m) * DH + k0 + kq * 4);
            As[kq*4+0][m] = v.x; As[kq*4+1][m] = v.y; As[kq*4+2][m] = v.z; As[kq*4+3][m] = v.w;
        }
#pragma unroll
        for (int i = 0; i < 2; i++) {
            int f = tid * 2 + i, n = f >> 2, kq = f & 3;
            float4 v = *reinterpret_cast<const float4*>(base + (size_t)(br0 + n) * 1024 + k0 + kq * 4);
            Bs[kq*4+0][n] = v.x; Bs[kq*4+1][n] = v.y; Bs[kq*4+2][n] = v.z; Bs[kq*4+3][n] = v.w;
        }
        __syncthreads();
#pragma unroll
        for (int kk = 0; kk < 16; kk++) {
            float4 a0 = *(const float4*)&As[kk][ty*8], a1 = *(const float4*)&As[kk][ty*8+4];
            float4 b0 = *(const float4*)&Bs[kk][tx*4], b1 = *(const float4*)&Bs[kk][64+tx*4];
            float a[8] = {a0.x,a0.y,a0.z,a0.w,a1.x,a1.y,a1.z,a1.w};
            float bb[8] = {b0.x,b0.y,b0.z,b0.w,b1.x,b1.y,b1.z,b1.w};
#pragma unroll
            for (int i = 0; i < 8; i++)
#pragma unroll
                for (int j = 0; j < 8; j++) acc[i][j] = fmaf(a[i], bb[j], acc[i][j]);
        }
        __syncthreads();
    }
#pragma unroll
    for (int i = 0; i < 8; i++) {
        size_t row = (size_t)(m0 + ty * 8 + i) * 1536;
        *(float4*)&g_G[row + n0 + tx*4]      = make_float4(acc[i][0],acc[i][1],acc[i][2],acc[i][3]);
        *(float4*)&g_G[row + n0 + 64 + tx*4] = make_float4(acc[i][4],acc[i][5],acc[i][6],acc[i][7]);
    }
}

// ================= helpers =================
__device__ __forceinline__ uint32_t smem_u32(const void* p) {
    return (uint32_t)__cvta_generic_to_shared(p);
}
__device__ __forceinline__ uint32_t dsmem_map(uint32_t a, unsigned r) {
    uint32_t x; asm("mapa.shared::cluster.u32 %0, %1, %2;" : "=r"(x) : "r"(a), "r"(r)); return x;
}
__device__ __forceinline__ void st_async64(uint32_t a, uint32_t mbar, float x, float y) {
    unsigned long long v = ((unsigned long long)__float_as_uint(y) << 32) | __float_as_uint(x);
    asm volatile("st.async.shared::cluster.mbarrier::complete_tx::bytes.u64 [%0], %1, [%2];"
                 :: "r"(a), "l"(v), "r"(mbar) : "memory");
}
__device__ __forceinline__ void mbar_init(uint32_t a, uint32_t cnt) {
    asm volatile("mbarrier.init.shared.b64 [%0], %1;" :: "r"(a), "r"(cnt) : "memory");
}
__device__ __forceinline__ void mbar_expect_tx(uint32_t a, uint32_t tx) {
    asm volatile("mbarrier.arrive.expect_tx.shared.b64 _, [%0], %1;" :: "r"(a), "r"(tx) : "memory");
}
__device__ __forceinline__ void mbar_wait(uint32_t a, uint32_t parity) {
    uint32_t done;
    asm volatile("{\n\t.reg .pred p;\n\t"
                 "mbarrier.try_wait.parity.shared.b64 p, [%1], %2, 0x989680;\n\t"
                 "selp.b32 %0, 1, 0, p;\n\t}"
                 : "=r"(done) : "r"(a), "r"(parity) : "memory");
    while (!done) {
        asm volatile("{\n\t.reg .pred p;\n\t"
                     "mbarrier.try_wait.parity.shared.b64 p, [%1], %2, 0x989680;\n\t"
                     "selp.b32 %0, 1, 0, p;\n\t}"
                     : "=r"(done) : "r"(a), "r"(parity) : "memory");
    }
}
__device__ __forceinline__ void cl_sync() {
    asm volatile("barrier.cluster.arrive.aligned;" ::: "memory");
    asm volatile("barrier.cluster.wait.aligned;"   ::: "memory");
}
__device__ __forceinline__ float sigmoidf_(float v) { return 1.f / (1.f + __expf(-v)); }
__device__ __forceinline__ float tanh_fast(float v) {
    float y; asm("tanh.approx.f32 %0, %1;" : "=f"(y) : "f"(v)); return y;
}

// 2 weight rows x 2 batch vectors, weights read ONCE. Full warp reduce of the
// 4 interleaved accumulators (also hides shfl latency).
__device__ __forceinline__ void dot2b(const float* wr0, const float* wr1,
                                      const float4* vA, const float4* vB, int l,
                                      float& a0, float& a1, float& b0, float& b1) {
    float x0 = 0.f, x1 = 0.f, y0 = 0.f, y1 = 0.f;
#pragma unroll
    for (int q = 0; q < 4; q++) {
        float4 w0 = *(const float4*)(wr0 + q * 128 + l * 4);
        float4 w1 = *(const float4*)(wr1 + q * 128 + l * 4);
        x0 = fmaf(w0.x, vA[q].x, x0); x0 = fmaf(w0.y, vA[q].y, x0);
        x0 = fmaf(w0.z, vA[q].z, x0); x0 = fmaf(w0.w, vA[q].w, x0);
        x1 = fmaf(w1.x, vA[q].x, x1); x1 = fmaf(w1.y, vA[q].y, x1);
        x1 = fmaf(w1.z, vA[q].z, x1); x1 = fmaf(w1.w, vA[q].w, x1);
        y0 = fmaf(w0.x, vB[q].x, y0); y0 = fmaf(w0.y, vB[q].y, y0);
        y0 = fmaf(w0.z, vB[q].z, y0); y0 = fmaf(w0.w, vB[q].w, y0);
        y1 = fmaf(w1.x, vB[q].x, y1); y1 = fmaf(w1.y, vB[q].y, y1);
        y1 = fmaf(w1.z, vB[q].z, y1); y1 = fmaf(w1.w, vB[q].w, y1);
    }
#pragma unroll
    for (int d = 16; d; d >>= 1) {
        x0 += __shfl_xor_sync(~0u, x0, d);
        x1 += __shfl_xor_sync(~0u, x1, d);
        y0 += __shfl_xor_sync(~0u, y0, d);
        y1 += __shfl_xor_sync(~0u, y1, d);
    }
    a0 = x0; a1 = x1; b0 = y0; b1 = y1;
}

// == GRU: 4 clusters x 16 CTAs x 512 thr; 2 batches share one weight read ======
__global__ void __cluster_dims__(CLUSTER, 1, 1) __launch_bounds__(512, 1)
gru_kernel(const float* __restrict__ Wz, const float* __restrict__ Wr,
           const float* __restrict__ Wh, const float* __restrict__ Wc,
           float* __restrict__ out) {
    extern __shared__ float sm[];
    float* wAll  = sm;                   // [96][512]: r 0-31, z 32-63, h 64-95
    float* hb[2]  = { sm + 96 * 512,        sm + 96 * 512 + 1024 };  // [2][512] each
    float* rb_[2] = { sm + 96 * 512 + 2048, sm + 96 * 512 + 3072 };  // [2][512] each
    uint32_t mbb = smem_u32(sm + 96 * 512 + 4096);
    uint32_t mb_rh[2] = { mbb, mbb + 8 };
    uint32_t mb_h[2]  = { mbb + 16, mbb + 24 };

    const int tid = threadIdx.x;
    unsigned rank; asm("mov.u32 %0, %%cluster_ctarank;" : "=r"(rank));
    const int b0 = 2 * (blockIdx.x / CLUSTER);
    const int j0 = (int)rank * RPC;
    const int w = tid >> 5, l = tid & 31;

    for (int i = tid; i < 32 * 128; i += 512) {
        int r = i >> 7, q = (i & 127) * 4;
        *(float4*)&wAll[r * 512 + q]        = *(const float4*)(Wr + (size_t)(j0 + r) * 1024 + 512 + q);
        *(float4*)&wAll[(32 + r) * 512 + q] = *(const float4*)(Wz + (size_t)(j0 + r) * 1024 + 512 + q);
        *(float4*)&wAll[(64 + r) * 512 + q] = *(const float4*)(Wh + (size_t)(j0 + r) * 1024 + 512 + q);
    }
    for (int i = tid; i < 1024; i += 512) { hb[0][i] = 0.f; hb[1][i] = 0.f; }
    if (tid == 0) {
        mbar_init(mb_rh[0], 1); mbar_init(mb_rh[1], 1);
        mbar_init(mb_h[0], 1);  mbar_init(mb_h[1], 1);
    }
    __syncthreads();

    const int r0 = 2 * w;                          // this warp's 2 local rows
    uint32_t rh_d[2][2], h_d[2][2], mrh_r[2], mh_r[2];
    if (l < 16) {
#pragma unroll
        for (int B = 0; B < 2; B++) {
            rh_d[B][0] = dsmem_map(smem_u32(&rb_[B][0 * 512 + j0 + r0]), (unsigned)l);
            rh_d[B][1] = dsmem_map(smem_u32(&rb_[B][1 * 512 + j0 + r0]), (unsigned)l);
            h_d[B][0]  = dsmem_map(smem_u32(&hb[B][0 * 512 + j0 + r0]), (unsigned)l);
            h_d[B][1]  = dsmem_map(smem_u32(&hb[B][1 * 512 + j0 + r0]), (unsigned)l);
            mrh_r[B] = dsmem_map(mb_rh[B], (unsigned)l);
            mh_r[B]  = dsmem_map(mb_h[B], (unsigned)l);
        }
    }
    const size_t gz_o = j0 + r0, gr_o = 512 + j0 + r0, gh_o = 1024 + j0 + r0;

    cl_sync();                                     // mbars + h0 + weights live

    float2 gr[2], gz[2], gh[2];
#pragma unroll
    for (int B = 0; B < 2; B++) {
        const size_t gb = (size_t)(b0 + B) * 1536;
        gr[B] = *(const float2*)(g_G + gb + gr_o);
        gz[B] = *(const float2*)(g_G + gb + gz_o);
        gh[B] = *(const float2*)(g_G + gb + gh_o);
    }

    int p = 0;
    uint32_t ph = 0;
    for (int t = 0; t < S_LEN; t++) {
        if (tid == 0) {
#pragma unroll
            for (int B = 0; B < 2; B++) {
                mbar_expect_tx(mb_rh[B], 2048);
                mbar_expect_tx(mb_h[B], 2048);
            }
        }
        const int tn = (t + 1 < S_LEN) ? t + 1 : t;
        const int rbix = t & 1;

        // ---- load both batches' h (each once, reused by r and z) ----
        float4 hA[4], hB[4];
#pragma unroll
        for (int q = 0; q < 4; q++) {
            hA[q] = *(const float4*)&hb[0][p * 512 + q * 128 + l * 4];
            hB[q] = *(const float4*)&hb[1][p * 512 + q * 128 + l * 4];
        }
        float2 hoA = *(const float2*)&hb[0][p * 512 + j0 + r0];
        float2 hoB = *(const float2*)&hb[1][p * 512 + j0 + r0];

        // ---- r gate: 2 rows x 2 batches with one weight read; push early ----
        {
            float a0, a1, c0, c1;
            dot2b(&wAll[r0 * 512], &wAll[(r0 + 1) * 512], hA, hB, l, a0, a1, c0, c1);
            if (l < 16) {
                st_async64(rh_d[0][rbix], mrh_r[0],
                           sigmoidf_(a0 + gr[0].x) * hoA.x,
                           sigmoidf_(a1 + gr[0].y) * hoA.y);
                st_async64(rh_d[1][rbix], mrh_r[1],
                           sigmoidf_(c0 + gr[1].x) * hoB.x,
                           sigmoidf_(c1 + gr[1].y) * hoB.y);
            }
        }

        // ---- z gate (both batches) in the fabric shadow; stays in registers ----
        float z0[2], z1[2];
        {
            float a0, a1, c0, c1;
            dot2b(&wAll[(32 + r0) * 512], &wAll[(33 + r0) * 512], hA, hB, l, a0, a1, c0, c1);
            z0[0] = sigmoidf_(a0 + gz[0].x); z1[0] = sigmoidf_(a1 + gz[0].y);
            z0[1] = sigmoidf_(c0 + gz[1].x); z1[1] = sigmoidf_(c1 + gz[1].y);
        }

        // prefetch next step's gate-x pre-acts (off critical path)
        float2 gnr[2], gnz[2], gnh[2];
#pragma unroll
        for (int B = 0; B < 2; B++) {
            const size_t gbn = ((size_t)tn * 8 + b0 + B) * 1536;
            gnr[B] = *(const float2*)(g_G + gbn + gr_o);
            gnz[B] = *(const float2*)(g_G + gbn + gz_o);
            gnh[B] = *(const float2*)(g_G + gbn + gh_o);
        }

        // ---- wait both r*h, then amortized h' for both batches ----
        mbar_wait(mb_rh[0], ph);
        mbar_wait(mb_rh[1], ph);
        float4 rA[4], rB[4];
#pragma unroll
        for (int q = 0; q < 4; q++) {
            rA[q] = *(const float4*)&rb_[0][rbix * 512 + q * 128 + l * 4];
            rB[q] = *(const float4*)&rb_[1][rbix * 512 + q * 128 + l * 4];
        }
        {
            float a0, a1, c0, c1;
            dot2b(&wAll[(64 + r0) * 512], &wAll[(65 + r0) * 512], rA, rB, l, a0, a1, c0, c1);
            if (l < 16) {
                float hn0 = hoA.x + z0[0] * (tanh_fast(a0 + gh[0].x) - hoA.x);
                float hn1 = hoA.y + z1[0] * (tanh_fast(a1 + gh[0].y) - hoA.y);
                st_async64(h_d[0][p ^ 1], mh_r[0], hn0, hn1);
                float hm0 = hoB.x + z0[1] * (tanh_fast(c0 + gh[1].x) - hoB.x);
                float hm1 = hoB.y + z1[1] * (tanh_fast(c1 + gh[1].y) - hoB.y);
                st_async64(h_d[1][p ^ 1], mh_r[1], hm0, hm1);
            }
        }
        mbar_wait(mb_h[0], ph);
        mbar_wait(mb_h[1], ph);

#pragma unroll
        for (int B = 0; B < 2; B++) { gr[B] = gnr[B]; gz[B] = gnz[B]; gh[B] = gnh[B]; }
        ph ^= 1; p ^= 1;
    }

    // classifier: final h in hb[B][0]; rank 0 writes out[b0+B][10]
    if (rank == 0 && w < 10) {
#pragma unroll
        for (int B = 0; B < 2; B++) {
            float s = 0.f;
            for (int k = l; k < DH; k += 32)
                s += hb[B][k] * Wc[(size_t)w * DH + k];
#pragma unroll
            for (int d = 16; d; d >>= 1) s += __shfl_xor_sync(~0u, s, d);
            if (l == 0) out[(b0 + B) * 10 + w] = s;
        }
    }
    cl_sync();                                     // no early-exit vs peer DSMEM
}

extern "C" void kernel_launch(void* const* d_in, const int* in_sizes, int n_in,
                              void* d_out, int out_size) {
    const float* x   = (const float*)d_in[0];
    const float* Wlm = (const float*)d_in[1];
    const float* Wz  = (const float*)d_in[2];
    const float* Wr  = (const float*)d_in[3];
    const float* Wh  = (const float*)d_in[4];
    const float* Wc  = (const float*)d_in[5];
    float* out = (float*)d_out;

    const int smem_bytes = (96 * 512 + 4 * 1024) * 4 + 32;
    cudaFuncSetAttribute(gru_kernel, cudaFuncAttributeNonPortableClusterSizeAllowed, 1);
    cudaFuncSetAttribute(gru_kernel, cudaFuncAttributeMaxDynamicSharedMemorySize, smem_bytes);

    gemm1_kernel<<<dim3(4, 256), 256>>>(x, Wlm);
    gemm2_kernel<<<dim3(12, 256), 256>>>(Wz, Wr, Wh);
    gru_kernel<<<(BATCH / 2) * CLUSTER, 512, smem_bytes>>>(Wz, Wr, Wh, Wc, out);
}

// round 14
// speedup vs baseline: 1.3486x; 1.0821x over previous
#include <cuda_runtime.h>
#include <cuda_bf16.h>
#include <cstdint>
#include <cstddef>

#define S_LEN 4096
#define BATCH 8
#define DH    512
#define DIN   2048
#define M_TOT (S_LEN * BATCH)
#define CLUSTER 16
#define RPC   32

// bf16 hi/lo operand arrays
__device__ __nv_bfloat16 g_xh[(size_t)M_TOT * DIN], g_xl[(size_t)M_TOT * DIN];
__device__ __nv_bfloat16 g_w1h[DH * DIN], g_w1l[DH * DIN];
__device__ __nv_bfloat16 g_seqh[(size_t)M_TOT * DH], g_seql[(size_t)M_TOT * DH];
__device__ __nv_bfloat16 g_w2h[3 * DH * DH], g_w2l[3 * DH * DH];
__device__ float g_G[(size_t)M_TOT * 3 * DH];

// ---------------- fp32 -> bf16 hi/lo split helpers ----------------
__device__ __forceinline__ uint32_t pack_split2(float x, float y, uint32_t& lo) {
    __nv_bfloat16 hx = __float2bfloat16(x), hy = __float2bfloat16(y);
    __nv_bfloat16 lx = __float2bfloat16(x - __bfloat162float(hx));
    __nv_bfloat16 ly = __float2bfloat16(y - __bfloat162float(hy));
    lo = ((uint32_t)__bfloat16_as_ushort(ly) << 16) | __bfloat16_as_ushort(lx);
    return ((uint32_t)__bfloat16_as_ushort(hy) << 16) | __bfloat16_as_ushort(hx);
}
__device__ __forceinline__ void split_store4(float4 v, __nv_bfloat16* ph, __nv_bfloat16* pl) {
    uint2 h, l;
    h.x = pack_split2(v.x, v.y, l.x);
    h.y = pack_split2(v.z, v.w, l.y);
    *reinterpret_cast<uint2*>(ph) = h;
    *reinterpret_cast<uint2*>(pl) = l;
}

// cvt_x: x[b][t][k] -> (m = t*8+b)-major hi/lo
__global__ __launch_bounds__(256) void cvt_x(const float* __restrict__ x) {
    size_t i4 = (size_t)blockIdx.x * 256 + threadIdx.x;     // 16,777,216 float4s
    int m = (int)(i4 >> 9), kq = (int)(i4 & 511);
    int b = m & 7, t = m >> 3;
    float4 v = reinterpret_cast<const float4*>(x)[((size_t)b * S_LEN + t) * 512 + kq];
    size_t o = (size_t)m * DIN + kq * 4;
    split_store4(v, g_xh + o, g_xl + o);
}
__global__ __launch_bounds__(256) void cvt_w1(const float* __restrict__ Wlm) {
    int i4 = blockIdx.x * 256 + threadIdx.x;                // 262,144 float4s
    float4 v = reinterpret_cast<const float4*>(Wlm)[i4];
    size_t o = (size_t)i4 * 4;
    split_store4(v, g_w1h + o, g_w1l + o);
}
__global__ __launch_bounds__(256) void cvt_w2(const float* __restrict__ Wz,
                                              const float* __restrict__ Wr,
                                              const float* __restrict__ Wh) {
    int i4 = blockIdx.x * 256 + threadIdx.x;                // 196,608 float4s
    int n = i4 >> 7, kq = i4 & 127;
    const float* W = (n < 512) ? Wz : (n < 1024) ? Wr : Wh;
    float4 v = reinterpret_cast<const float4*>(W + (size_t)(n & 511) * 1024)[kq];  // x-half
    size_t o = (size_t)n * DH + kq * 4;
    split_store4(v, g_w2h + o, g_w2l + o);
}

// ---------------- bf16x3 tensor-core GEMM: C = A[M,K] * B[N,K]^T ----------------
__device__ __forceinline__ void cp16(uint32_t dst, const void* src) {
    asm volatile("cp.async.cg.shared.global [%0], [%1], 16;" :: "r"(dst), "l"(src));
}
#define MMA_BF16(c, a0, a1, a2, a3, b0, b1) \
    asm volatile("mma.sync.aligned.m16n8k16.row.col.f32.bf16.bf16.f32 " \
        "{%0,%1,%2,%3}, {%4,%5,%6,%7}, {%8,%9}, {%0,%1,%2,%3};" \
        : "+f"((c)[0]), "+f"((c)[1]), "+f"((c)[2]), "+f"((c)[3]) \
        : "r"(a0), "r"(a1), "r"(a2), "r"(a3), "r"(b0), "r"(b1))

__global__ __launch_bounds__(256) void mma_gemm(
    const __nv_bfloat16* __restrict__ Ah, const __nv_bfloat16* __restrict__ Al,
    const __nv_bfloat16* __restrict__ Bh, const __nv_bfloat16* __restrict__ Bl,
    float* __restrict__ Cf, __nv_bfloat16* __restrict__ Ch, __nv_bfloat16* __restrict__ Cl,
    int K, int N)
{
    extern __shared__ uint32_t sw[];    // 2 stages x {Ah,Al,Bh,Bl} x 128 rows x 12 words
    const int tid = threadIdx.x;
    const int m0 = blockIdx.y * 128, n0 = blockIdx.x * 128;
    const int w = tid >> 5, l = tid & 31;
    const int wm = (w >> 2) * 64, wn = (w & 3) * 32;
    const int lq = l >> 2, lr = l & 3;
    const int row = tid >> 1, half = tid & 1;
    const uint32_t sbase = (uint32_t)__cvta_generic_to_shared(sw);
    const int NK = K >> 4;

    float acc[4][4][4];
#pragma unroll
    for (int a = 0; a < 4; a++)
#pragma unroll
        for (int b = 0; b < 4; b++)
#pragma unroll
            for (int c = 0; c < 4; c++) acc[a][b][c] = 0.f;

    const size_t arow = (size_t)(m0 + row) * K + half * 8;
    const size_t brow = (size_t)(n0 + row) * K + half * 8;
    {   // prologue: chunk 0 -> stage 0
        uint32_t d = sbase + (row * 12 + half * 4) * 4;
        cp16(d,         Ah + arow);
        cp16(d + 6144,  Al + arow);
        cp16(d + 12288, Bh + brow);
        cp16(d + 18432, Bl + brow);
        asm volatile("cp.async.commit_group;" ::: "memory");
    }
    for (int i = 0; i < NK; i++) {
        asm volatile("cp.async.wait_group 0;" ::: "memory");
        __syncthreads();
        const int st = i & 1;
        if (i + 1 < NK) {
            const int k0 = (i + 1) << 4;
            uint32_t d = sbase + ((st ^ 1) * 6144 + row * 12 + half * 4) * 4;
            cp16(d,         Ah + arow + k0);
            cp16(d + 6144,  Al + arow + k0);
            cp16(d + 12288, Bh + brow + k0);
            cp16(d + 18432, Bl + brow + k0);
            asm volatile("cp.async.commit_group;" ::: "memory");
        }
        const uint32_t* S = sw + st * 6144;
        uint32_t bh0[4], bh1[4], bl0[4], bl1[4];
#pragma unroll
        for (int nt = 0; nt < 4; nt++) {
            int o = 3072 + (wn + nt * 8 + lq) * 12 + lr;
            bh0[nt] = S[o]; bh1[nt] = S[o + 4];
            bl0[nt] = S[o + 1536]; bl1[nt] = S[o + 1540];
        }
#pragma unroll
        for (int mt = 0; mt < 4; mt++) {
            int m = wm + mt * 16 + lq;
            int o1 = m * 12 + lr, o2 = (m + 8) * 12 + lr;
            uint32_t ah0 = S[o1], ah1 = S[o2], ah2 = S[o1 + 4], ah3 = S[o2 + 4];
            uint32_t al0 = S[o1 + 1536], al1 = S[o2 + 1536];
            uint32_t al2 = S[o1 + 1540], al3 = S[o2 + 1540];
#pragma unroll
            for (int nt = 0; nt < 4; nt++) {
                MMA_BF16(acc[mt][nt], ah0, ah1, ah2, ah3, bh0[nt], bh1[nt]);
                MMA_BF16(acc[mt][nt], ah0, ah1, ah2, ah3, bl0[nt], bl1[nt]);
                MMA_BF16(acc[mt][nt], al0, al1, al2, al3, bh0[nt], bh1[nt]);
            }
        }
    }
    // epilogue
#pragma unroll
    for (int mt = 0; mt < 4; mt++) {
#pragma unroll
        for (int nt = 0; nt < 4; nt++) {
            int m = m0 + wm + mt * 16 + lq;
            int c = n0 + wn + nt * 8 + lr * 2;
            const float* a = acc[mt][nt];
            if (Cf) {
                *reinterpret_cast<float2*>(Cf + (size_t)m * N + c)       = make_float2(a[0], a[1]);
                *reinterpret_cast<float2*>(Cf + (size_t)(m + 8) * N + c) = make_float2(a[2], a[3]);
            } else {
                uint32_t lo0, lo1;
                uint32_t hi0 = pack_split2(a[0], a[1], lo0);
                uint32_t hi1 = pack_split2(a[2], a[3], lo1);
                *reinterpret_cast<uint32_t*>(Ch + (size_t)m * N + c)       = hi0;
                *reinterpret_cast<uint32_t*>(Cl + (size_t)m * N + c)       = lo0;
                *reinterpret_cast<uint32_t*>(Ch + (size_t)(m + 8) * N + c) = hi1;
                *reinterpret_cast<uint32_t*>(Cl + (size_t)(m + 8) * N + c) = lo1;
            }
        }
    }
}

// ================= GRU helpers (unchanged from R12) =================
__device__ __forceinline__ uint32_t smem_u32(const void* p) {
    return (uint32_t)__cvta_generic_to_shared(p);
}
__device__ __forceinline__ uint32_t dsmem_map(uint32_t a, unsigned r) {
    uint32_t x; asm("mapa.shared::cluster.u32 %0, %1, %2;" : "=r"(x) : "r"(a), "r"(r)); return x;
}
__device__ __forceinline__ void st_async64(uint32_t a, uint32_t mbar, float x, float y) {
    unsigned long long v = ((unsigned long long)__float_as_uint(y) << 32) | __float_as_uint(x);
    asm volatile("st.async.shared::cluster.mbarrier::complete_tx::bytes.u64 [%0], %1, [%2];"
                 :: "r"(a), "l"(v), "r"(mbar) : "memory");
}
__device__ __forceinline__ void mbar_init(uint32_t a, uint32_t cnt) {
    asm volatile("mbarrier.init.shared.b64 [%0], %1;" :: "r"(a), "r"(cnt) : "memory");
}
__device__ __forceinline__ void mbar_expect_tx(uint32_t a, uint32_t tx) {
    asm volatile("mbarrier.arrive.expect_tx.shared.b64 _, [%0], %1;" :: "r"(a), "r"(tx) : "memory");
}
__device__ __forceinline__ void mbar_wait(uint32_t a, uint32_t parity) {
    uint32_t done;
    asm volatile("{\n\t.reg .pred p;\n\t"
                 "mbarrier.try_wait.parity.shared.b64 p, [%1], %2, 0x989680;\n\t"
                 "selp.b32 %0, 1, 0, p;\n\t}"
                 : "=r"(done) : "r"(a), "r"(parity) : "memory");
    while (!done) {
        asm volatile("{\n\t.reg .pred p;\n\t"
                     "mbarrier.try_wait.parity.shared.b64 p, [%1], %2, 0x989680;\n\t"
                     "selp.b32 %0, 1, 0, p;\n\t}"
                     : "=r"(done) : "r"(a), "r"(parity) : "memory");
    }
}
__device__ __forceinline__ void cl_sync() {
    asm volatile("barrier.cluster.arrive.aligned;" ::: "memory");
    asm volatile("barrier.cluster.wait.aligned;"   ::: "memory");
}
__device__ __forceinline__ float sigmoidf_(float v) { return 1.f / (1.f + __expf(-v)); }
__device__ __forceinline__ float tanh_fast(float v) {
    float y; asm("tanh.approx.f32 %0, %1;" : "=f"(y) : "f"(v)); return y;
}
__device__ __forceinline__ void dot2b(const float* wr0, const float* wr1,
                                      const float4* vA, const float4* vB, int l,
                                      float& a0, float& a1, float& b0, float& b1) {
    float x0 = 0.f, x1 = 0.f, y0 = 0.f, y1 = 0.f;
#pragma unroll
    for (int q = 0; q < 4; q++) {
        float4 w0 = *(const float4*)(wr0 + q * 128 + l * 4);
        float4 w1 = *(const float4*)(wr1 + q * 128 + l * 4);
        x0 = fmaf(w0.x, vA[q].x, x0); x0 = fmaf(w0.y, vA[q].y, x0);
        x0 = fmaf(w0.z, vA[q].z, x0); x0 = fmaf(w0.w, vA[q].w, x0);
        x1 = fmaf(w1.x, vA[q].x, x1); x1 = fmaf(w1.y, vA[q].y, x1);
        x1 = fmaf(w1.z, vA[q].z, x1); x1 = fmaf(w1.w, vA[q].w, x1);
        y0 = fmaf(w0.x, vB[q].x, y0); y0 = fmaf(w0.y, vB[q].y, y0);
        y0 = fmaf(w0.z, vB[q].z, y0); y0 = fmaf(w0.w, vB[q].w, y0);
        y1 = fmaf(w1.x, vB[q].x, y1); y1 = fmaf(w1.y, vB[q].y, y1);
        y1 = fmaf(w1.z, vB[q].z, y1); y1 = fmaf(w1.w, vB[q].w, y1);
    }
#pragma unroll
    for (int d = 16; d; d >>= 1) {
        x0 += __shfl_xor_sync(~0u, x0, d);
        x1 += __shfl_xor_sync(~0u, x1, d);
        y0 += __shfl_xor_sync(~0u, y0, d);
        y1 += __shfl_xor_sync(~0u, y1, d);
    }
    a0 = x0; a1 = x1; b0 = y0; b1 = y1;
}

// == GRU: 4 clusters x 16 CTAs x 512 thr; 2 batches share one weight read (R12) =
__global__ void __cluster_dims__(CLUSTER, 1, 1) __launch_bounds__(512, 1)
gru_kernel(const float* __restrict__ Wz, const float* __restrict__ Wr,
           const float* __restrict__ Wh, const float* __restrict__ Wc,
           float* __restrict__ out) {
    extern __shared__ float sm[];
    float* wAll  = sm;
    float* hb[2]  = { sm + 96 * 512,        sm + 96 * 512 + 1024 };
    float* rb_[2] = { sm + 96 * 512 + 2048, sm + 96 * 512 + 3072 };
    uint32_t mbb = smem_u32(sm + 96 * 512 + 4096);
    uint32_t mb_rh[2] = { mbb, mbb + 8 };
    uint32_t mb_h[2]  = { mbb + 16, mbb + 24 };

    const int tid = threadIdx.x;
    unsigned rank; asm("mov.u32 %0, %%cluster_ctarank;" : "=r"(rank));
    const int b0 = 2 * (blockIdx.x / CLUSTER);
    const int j0 = (int)rank * RPC;
    const int w = tid >> 5, l = tid & 31;

    for (int i = tid; i < 32 * 128; i += 512) {
        int r = i >> 7, q = (i & 127) * 4;
        *(float4*)&wAll[r * 512 + q]        = *(const float4*)(Wr + (size_t)(j0 + r) * 1024 + 512 + q);
        *(float4*)&wAll[(32 + r) * 512 + q] = *(const float4*)(Wz + (size_t)(j0 + r) * 1024 + 512 + q);
        *(float4*)&wAll[(64 + r) * 512 + q] = *(const float4*)(Wh + (size_t)(j0 + r) * 1024 + 512 + q);
    }
    for (int i = tid; i < 1024; i += 512) { hb[0][i] = 0.f; hb[1][i] = 0.f; }
    if (tid == 0) {
        mbar_init(mb_rh[0], 1); mbar_init(mb_rh[1], 1);
        mbar_init(mb_h[0], 1);  mbar_init(mb_h[1], 1);
    }
    __syncthreads();

    const int r0 = 2 * w;
    uint32_t rh_d[2][2], h_d[2][2], mrh_r[2], mh_r[2];
    if (l < 16) {
#pragma unroll
        for (int B = 0; B < 2; B++) {
            rh_d[B][0] = dsmem_map(smem_u32(&rb_[B][0 * 512 + j0 + r0]), (unsigned)l);
            rh_d[B][1] = dsmem_map(smem_u32(&rb_[B][1 * 512 + j0 + r0]), (unsigned)l);
            h_d[B][0]  = dsmem_map(smem_u32(&hb[B][0 * 512 + j0 + r0]), (unsigned)l);
            h_d[B][1]  = dsmem_map(smem_u32(&hb[B][1 * 512 + j0 + r0]), (unsigned)l);
            mrh_r[B] = dsmem_map(mb_rh[B], (unsigned)l);
            mh_r[B]  = dsmem_map(mb_h[B], (unsigned)l);
        }
    }
    const size_t gz_o = j0 + r0, gr_o = 512 + j0 + r0, gh_o = 1024 + j0 + r0;

    cl_sync();

    float2 gr[2], gz[2], gh[2];
#pragma unroll
    for (int B = 0; B < 2; B++) {
        const size_t gb = (size_t)(b0 + B) * 1536;
        gr[B] = *(const float2*)(g_G + gb + gr_o);
        gz[B] = *(const float2*)(g_G + gb + gz_o);
        gh[B] = *(const float2*)(g_G + gb + gh_o);
    }

    int p = 0;
    uint32_t ph = 0;
    for (int t = 0; t < S_LEN; t++) {
        if (tid == 0) {
#pragma unroll
            for (int B = 0; B < 2; B++) {
                mbar_expect_tx(mb_rh[B], 2048);
                mbar_expect_tx(mb_h[B], 2048);
            }
        }
        const int tn = (t + 1 < S_LEN) ? t + 1 : t;
        const int rbix = t & 1;

        float4 hA[4], hB[4];
#pragma unroll
        for (int q = 0; q < 4; q++) {
            hA[q] = *(const float4*)&hb[0][p * 512 + q * 128 + l * 4];
            hB[q] = *(const float4*)&hb[1][p * 512 + q * 128 + l * 4];
        }
        float2 hoA = *(const float2*)&hb[0][p * 512 + j0 + r0];
        float2 hoB = *(const float2*)&hb[1][p * 512 + j0 + r0];

        {
            float a0, a1, c0, c1;
            dot2b(&wAll[r0 * 512], &wAll[(r0 + 1) * 512], hA, hB, l, a0, a1, c0, c1);
            if (l < 16) {
                st_async64(rh_d[0][rbix], mrh_r[0],
                           sigmoidf_(a0 + gr[0].x) * hoA.x,
                           sigmoidf_(a1 + gr[0].y) * hoA.y);
                st_async64(rh_d[1][rbix], mrh_r[1],
                           sigmoidf_(c0 + gr[1].x) * hoB.x,
                           sigmoidf_(c1 + gr[1].y) * hoB.y);
            }
        }
        float z0[2], z1[2];
        {
            float a0, a1, c0, c1;
            dot2b(&wAll[(32 + r0) * 512], &wAll[(33 + r0) * 512], hA, hB, l, a0, a1, c0, c1);
            z0[0] = sigmoidf_(a0 + gz[0].x); z1[0] = sigmoidf_(a1 + gz[0].y);
            z0[1] = sigmoidf_(c0 + gz[1].x); z1[1] = sigmoidf_(c1 + gz[1].y);
        }
        float2 gnr[2], gnz[2], gnh[2];
#pragma unroll
        for (int B = 0; B < 2; B++) {
            const size_t gbn = ((size_t)tn * 8 + b0 + B) * 1536;
            gnr[B] = *(const float2*)(g_G + gbn + gr_o);
            gnz[B] = *(const float2*)(g_G + gbn + gz_o);
            gnh[B] = *(const float2*)(g_G + gbn + gh_o);
        }
        mbar_wait(mb_rh[0], ph);
        mbar_wait(mb_rh[1], ph);
        float4 rA[4], rB[4];
#pragma unroll
        for (int q = 0; q < 4; q++) {
            rA[q] = *(const float4*)&rb_[0][rbix * 512 + q * 128 + l * 4];
            rB[q] = *(const float4*)&rb_[1][rbix * 512 + q * 128 + l * 4];
        }
        {
            float a0, a1, c0, c1;
            dot2b(&wAll[(64 + r0) * 512], &wAll[(65 + r0) * 512], rA, rB, l, a0, a1, c0, c1);
            if (l < 16) {
                float hn0 = hoA.x + z0[0] * (tanh_fast(a0 + gh[0].x) - hoA.x);
                float hn1 = hoA.y + z1[0] * (tanh_fast(a1 + gh[0].y) - hoA.y);
                st_async64(h_d[0][p ^ 1], mh_r[0], hn0, hn1);
                float hm0 = hoB.x + z0[1] * (tanh_fast(c0 + gh[1].x) - hoB.x);
                float hm1 = hoB.y + z1[1] * (tanh_fast(c1 + gh[1].y) - hoB.y);
                st_async64(h_d[1][p ^ 1], mh_r[1], hm0, hm1);
            }
        }
        mbar_wait(mb_h[0], ph);
        mbar_wait(mb_h[1], ph);
#pragma unroll
        for (int B = 0; B < 2; B++) { gr[B] = gnr[B]; gz[B] = gnz[B]; gh[B] = gnh[B]; }
        ph ^= 1; p ^= 1;
    }

    if (rank == 0 && w < 10) {
#pragma unroll
        for (int B = 0; B < 2; B++) {
            float s = 0.f;
            for (int k = l; k < DH; k += 32)
                s += hb[B][k] * Wc[(size_t)w * DH + k];
#pragma unroll
            for (int d = 16; d; d >>= 1) s += __shfl_xor_sync(~0u, s, d);
            if (l == 0) out[(b0 + B) * 10 + w] = s;
        }
    }
    cl_sync();
}

extern "C" void kernel_launch(void* const* d_in, const int* in_sizes, int n_in,
                              void* d_out, int out_size) {
    const float* x   = (const float*)d_in[0];
    const float* Wlm = (const float*)d_in[1];
    const float* Wz  = (const float*)d_in[2];
    const float* Wr  = (const float*)d_in[3];
    const float* Wh  = (const float*)d_in[4];
    const float* Wc  = (const float*)d_in[5];
    float* out = (float*)d_out;

    const int gemm_smem = 49152;
    const int gru_smem = (96 * 512 + 4 * 1024) * 4 + 32;
    cudaFuncSetAttribute(mma_gemm, cudaFuncAttributeMaxDynamicSharedMemorySize, gemm_smem);
    cudaFuncSetAttribute(gru_kernel, cudaFuncAttributeNonPortableClusterSizeAllowed, 1);
    cudaFuncSetAttribute(gru_kernel, cudaFuncAttributeMaxDynamicSharedMemorySize, gru_smem);

    __nv_bfloat16 *xh, *xl, *w1h, *w1l, *sh, *sl, *w2h, *w2l;
    float* G;
    cudaGetSymbolAddress((void**)&xh, g_xh);   cudaGetSymbolAddress((void**)&xl, g_xl);
    cudaGetSymbolAddress((void**)&w1h, g_w1h); cudaGetSymbolAddress((void**)&w1l, g_w1l);
    cudaGetSymbolAddress((void**)&sh, g_seqh); cudaGetSymbolAddress((void**)&sl, g_seql);
    cudaGetSymbolAddress((void**)&w2h, g_w2h); cudaGetSymbolAddress((void**)&w2l, g_w2l);
    cudaGetSymbolAddress((void**)&G, g_G);

    cvt_x<<<65536, 256>>>(x);
    cvt_w1<<<1024, 256>>>(Wlm);
    cvt_w2<<<768, 256>>>(Wz, Wr, Wh);
    // GEMM1: seq(hi/lo) = x @ Wlm^T
    mma_gemm<<<dim3(4, 256), 256, gemm_smem>>>(xh, xl, w1h, w1l,
                                               nullptr, sh, sl, DIN, DH);
    // GEMM2: G = seq @ [Wzx|Wrx|Whx]^T
    mma_gemm<<<dim3(12, 256), 256, gemm_smem>>>(sh, sl, w2h, w2l,
                                                G, nullptr, nullptr, DH, 3 * DH);
    gru_kernel<<<(BATCH / 2) * CLUSTER, 512, gru_smem>>>(Wz, Wr, Wh, Wc, out);
}

// round 15
// speedup vs baseline: 2.1426x; 1.5888x over previous
#include <cuda_runtime.h>
#include <cuda_bf16.h>
#include <cstdint>
#include <cstddef>

#define S_LEN 4096
#define BATCH 8
#define DH    512
#define DIN   2048
#define M_TOT (S_LEN * BATCH)
#define CLUSTER 16

// bf16 hi/lo operand arrays (GEMM phase, unchanged from R13)
__device__ __nv_bfloat16 g_xh[(size_t)M_TOT * DIN], g_xl[(size_t)M_TOT * DIN];
__device__ __nv_bfloat16 g_w1h[DH * DIN], g_w1l[DH * DIN];
__device__ __nv_bfloat16 g_seqh[(size_t)M_TOT * DH], g_seql[(size_t)M_TOT * DH];
__device__ __nv_bfloat16 g_w2h[3 * DH * DH], g_w2l[3 * DH * DH];
__device__ float g_G[(size_t)M_TOT * 3 * DH];

__device__ __forceinline__ uint32_t pack_split2(float x, float y, uint32_t& lo) {
    __nv_bfloat16 hx = __float2bfloat16(x), hy = __float2bfloat16(y);
    __nv_bfloat16 lx = __float2bfloat16(x - __bfloat162float(hx));
    __nv_bfloat16 ly = __float2bfloat16(y - __bfloat162float(hy));
    lo = ((uint32_t)__bfloat16_as_ushort(ly) << 16) | __bfloat16_as_ushort(lx);
    return ((uint32_t)__bfloat16_as_ushort(hy) << 16) | __bfloat16_as_ushort(hx);
}
__device__ __forceinline__ void split_store4(float4 v, __nv_bfloat16* ph, __nv_bfloat16* pl) {
    uint2 h, l;
    h.x = pack_split2(v.x, v.y, l.x);
    h.y = pack_split2(v.z, v.w, l.y);
    *reinterpret_cast<uint2*>(ph) = h;
    *reinterpret_cast<uint2*>(pl) = l;
}

__global__ __launch_bounds__(256) void cvt_x(const float* __restrict__ x) {
    size_t i4 = (size_t)blockIdx.x * 256 + threadIdx.x;
    int m = (int)(i4 >> 9), kq = (int)(i4 & 511);
    int b = m & 7, t = m >> 3;
    float4 v = reinterpret_cast<const float4*>(x)[((size_t)b * S_LEN + t) * 512 + kq];
    size_t o = (size_t)m * DIN + kq * 4;
    split_store4(v, g_xh + o, g_xl + o);
}
__global__ __launch_bounds__(256) void cvt_w1(const float* __restrict__ Wlm) {
    int i4 = blockIdx.x * 256 + threadIdx.x;
    float4 v = reinterpret_cast<const float4*>(Wlm)[i4];
    size_t o = (size_t)i4 * 4;
    split_store4(v, g_w1h + o, g_w1l + o);
}
__global__ __launch_bounds__(256) void cvt_w2(const float* __restrict__ Wz,
                                              const float* __restrict__ Wr,
                                              const float* __restrict__ Wh) {
    int i4 = blockIdx.x * 256 + threadIdx.x;
    int n = i4 >> 7, kq = i4 & 127;
    const float* W = (n < 512) ? Wz : (n < 1024) ? Wr : Wh;
    float4 v = reinterpret_cast<const float4*>(W + (size_t)(n & 511) * 1024)[kq];
    size_t o = (size_t)n * DH + kq * 4;
    split_store4(v, g_w2h + o, g_w2l + o);
}

// ---------------- bf16x3 tensor-core GEMM (unchanged from R13) ----------------
__device__ __forceinline__ void cp16(uint32_t dst, const void* src) {
    asm volatile("cp.async.cg.shared.global [%0], [%1], 16;" :: "r"(dst), "l"(src));
}
#define MMA_BF16(c, a0, a1, a2, a3, b0, b1) \
    asm volatile("mma.sync.aligned.m16n8k16.row.col.f32.bf16.bf16.f32 " \
        "{%0,%1,%2,%3}, {%4,%5,%6,%7}, {%8,%9}, {%0,%1,%2,%3};" \
        : "+f"((c)[0]), "+f"((c)[1]), "+f"((c)[2]), "+f"((c)[3]) \
        : "r"(a0), "r"(a1), "r"(a2), "r"(a3), "r"(b0), "r"(b1))

__global__ __launch_bounds__(256) void mma_gemm(
    const __nv_bfloat16* __restrict__ Ah, const __nv_bfloat16* __restrict__ Al,
    const __nv_bfloat16* __restrict__ Bh, const __nv_bfloat16* __restrict__ Bl,
    float* __restrict__ Cf, __nv_bfloat16* __restrict__ Ch, __nv_bfloat16* __restrict__ Cl,
    int K, int N)
{
    extern __shared__ uint32_t sw[];
    const int tid = threadIdx.x;
    const int m0 = blockIdx.y * 128, n0 = blockIdx.x * 128;
    const int w = tid >> 5, l = tid & 31;
    const int wm = (w >> 2) * 64, wn = (w & 3) * 32;
    const int lq = l >> 2, lr = l & 3;
    const int row = tid >> 1, half = tid & 1;
    const uint32_t sbase = (uint32_t)__cvta_generic_to_shared(sw);
    const int NK = K >> 4;

    float acc[4][4][4];
#pragma unroll
    for (int a = 0; a < 4; a++)
#pragma unroll
        for (int b = 0; b < 4; b++)
#pragma unroll
            for (int c = 0; c < 4; c++) acc[a][b][c] = 0.f;

    const size_t arow = (size_t)(m0 + row) * K + half * 8;
    const size_t brow = (size_t)(n0 + row) * K + half * 8;
    {
        uint32_t d = sbase + (row * 12 + half * 4) * 4;
        cp16(d,         Ah + arow);
        cp16(d + 6144,  Al + arow);
        cp16(d + 12288, Bh + brow);
        cp16(d + 18432, Bl + brow);
        asm volatile("cp.async.commit_group;" ::: "memory");
    }
    for (int i = 0; i < NK; i++) {
        asm volatile("cp.async.wait_group 0;" ::: "memory");
        __syncthreads();
        const int st = i & 1;
        if (i + 1 < NK) {
            const int k0 = (i + 1) << 4;
            uint32_t d = sbase + ((st ^ 1) * 6144 + row * 12 + half * 4) * 4;
            cp16(d,         Ah + arow + k0);
            cp16(d + 6144,  Al + arow + k0);
            cp16(d + 12288, Bh + brow + k0);
            cp16(d + 18432, Bl + brow + k0);
            asm volatile("cp.async.commit_group;" ::: "memory");
        }
        const uint32_t* S = sw + st * 6144;
        uint32_t bh0[4], bh1[4], bl0[4], bl1[4];
#pragma unroll
        for (int nt = 0; nt < 4; nt++) {
            int o = 3072 + (wn + nt * 8 + lq) * 12 + lr;
            bh0[nt] = S[o]; bh1[nt] = S[o + 4];
            bl0[nt] = S[o + 1536]; bl1[nt] = S[o + 1540];
        }
#pragma unroll
        for (int mt = 0; mt < 4; mt++) {
            int m = wm + mt * 16 + lq;
            int o1 = m * 12 + lr, o2 = (m + 8) * 12 + lr;
            uint32_t ah0 = S[o1], ah1 = S[o2], ah2 = S[o1 + 4], ah3 = S[o2 + 4];
            uint32_t al0 = S[o1 + 1536], al1 = S[o2 + 1536];
            uint32_t al2 = S[o1 + 1540], al3 = S[o2 + 1540];
#pragma unroll
            for (int nt = 0; nt < 4; nt++) {
                MMA_BF16(acc[mt][nt], ah0, ah1, ah2, ah3, bh0[nt], bh1[nt]);
                MMA_BF16(acc[mt][nt], ah0, ah1, ah2, ah3, bl0[nt], bl1[nt]);
                MMA_BF16(acc[mt][nt], al0, al1, al2, al3, bh0[nt], bh1[nt]);
            }
        }
    }
#pragma unroll
    for (int mt = 0; mt < 4; mt++) {
#pragma unroll
        for (int nt = 0; nt < 4; nt++) {
            int m = m0 + wm + mt * 16 + lq;
            int c = n0 + wn + nt * 8 + lr * 2;
            const float* a = acc[mt][nt];
            if (Cf) {
                *reinterpret_cast<float2*>(Cf + (size_t)m * N + c)       = make_float2(a[0], a[1]);
                *reinterpret_cast<float2*>(Cf + (size_t)(m + 8) * N + c) = make_float2(a[2], a[3]);
            } else {
                uint32_t lo0, lo1;
                uint32_t hi0 = pack_split2(a[0], a[1], lo0);
                uint32_t hi1 = pack_split2(a[2], a[3], lo1);
                *reinterpret_cast<uint32_t*>(Ch + (size_t)m * N + c)       = hi0;
                *reinterpret_cast<uint32_t*>(Cl + (size_t)m * N + c)       = lo0;
                *reinterpret_cast<uint32_t*>(Ch + (size_t)(m + 8) * N + c) = hi1;
                *reinterpret_cast<uint32_t*>(Cl + (size_t)(m + 8) * N + c) = lo1;
            }
        }
    }
}

// ================= cluster / mbarrier helpers =================
__device__ __forceinline__ uint32_t smem_u32(const void* p) {
    return (uint32_t)__cvta_generic_to_shared(p);
}
__device__ __forceinline__ uint32_t dsmem_map(uint32_t a, unsigned r) {
    uint32_t x; asm("mapa.shared::cluster.u32 %0, %1, %2;" : "=r"(x) : "r"(a), "r"(r)); return x;
}
__device__ __forceinline__ void st_async32(uint32_t a, uint32_t mbar, float x) {
    asm volatile("st.async.shared::cluster.mbarrier::complete_tx::bytes.b32 [%0], %1, [%2];"
                 :: "r"(a), "r"(__float_as_uint(x)), "r"(mbar) : "memory");
}
__device__ __forceinline__ void st_async64(uint32_t a, uint32_t mbar, float x, float y) {
    unsigned long long v = ((unsigned long long)__float_as_uint(y) << 32) | __float_as_uint(x);
    asm volatile("st.async.shared::cluster.mbarrier::complete_tx::bytes.u64 [%0], %1, [%2];"
                 :: "r"(a), "l"(v), "r"(mbar) : "memory");
}
__device__ __forceinline__ void st_async128(uint32_t a, uint32_t mbar,
                                            float x, float y, float z, float w) {
    asm volatile("st.async.shared::cluster.mbarrier::complete_tx::bytes.v4.b32 "
                 "[%0], {%1,%2,%3,%4}, [%5];"
                 :: "r"(a), "r"(__float_as_uint(x)), "r"(__float_as_uint(y)),
                    "r"(__float_as_uint(z)), "r"(__float_as_uint(w)), "r"(mbar) : "memory");
}
__device__ __forceinline__ void mbar_init(uint32_t a, uint32_t cnt) {
    asm volatile("mbarrier.init.shared.b64 [%0], %1;" :: "r"(a), "r"(cnt) : "memory");
}
__device__ __forceinline__ void mbar_expect_tx(uint32_t a, uint32_t tx) {
    asm volatile("mbarrier.arrive.expect_tx.shared.b64 _, [%0], %1;" :: "r"(a), "r"(tx) : "memory");
}
__device__ __forceinline__ void mbar_wait(uint32_t a, uint32_t parity) {
    uint32_t done;
    asm volatile("{\n\t.reg .pred p;\n\t"
                 "mbarrier.try_wait.parity.shared.b64 p, [%1], %2, 0x989680;\n\t"
                 "selp.b32 %0, 1, 0, p;\n\t}"
                 : "=r"(done) : "r"(a), "r"(parity) : "memory");
    while (!done) {
        asm volatile("{\n\t.reg .pred p;\n\t"
                     "mbarrier.try_wait.parity.shared.b64 p, [%1], %2, 0x989680;\n\t"
                     "selp.b32 %0, 1, 0, p;\n\t}"
                     : "=r"(done) : "r"(a), "r"(parity) : "memory");
    }
}
__device__ __forceinline__ void cl_sync() {
    asm volatile("barrier.cluster.arrive.aligned;" ::: "memory");
    asm volatile("barrier.cluster.wait.aligned;"   ::: "memory");
}
__device__ __forceinline__ float sigmoidf_(float v) { return 1.f / (1.f + __expf(-v)); }
__device__ __forceinline__ float tanh_fast(float v) {
    float y; asm("tanh.approx.f32 %0, %1;" : "=f"(y) : "f"(v)); return y;
}

// ==== k-sliced GRU: 4 clusters x 16 CTAs x 512 thr; h fully CTA-local ==========
// CTA rank c owns h rows [32c,32c+32) AND weight columns (k-slice) [32c,32c+32).
// Per step: all threads compute z/r partials for global row=tid over the local
// k-slice (the CTA's own h rows) -> reduce-scatter (warp w -> rank w) -> owner
// sums, gates, forms r*h locally -> h' partials -> reduce-scatter -> owner
// tanh + h update, all local. No h broadcast, no shfl reduces.
// smem (floats): wT[3][32][512]=49152 | pz@49152 [16][32][4] | phh@51200 [16][32][2]
//   hloc@52224 [2][32] | rhloc@52288 [2][32] | zloc@52352 [2][32] | pcls@52416 [16][20]
//   mbars at float 52736: pz, phh, cls
__global__ void __cluster_dims__(CLUSTER, 1, 1) __launch_bounds__(512, 1)
gru_kernel(const float* __restrict__ Wz, const float* __restrict__ Wr,
           const float* __restrict__ Wh, const float* __restrict__ Wc,
           float* __restrict__ out) {
    extern __shared__ float sm[];
    float* wT    = sm;
    float* pz    = sm + 49152;
    float* phh   = sm + 51200;
    float* hloc  = sm + 52224;
    float* rhloc = sm + 52288;
    float* zloc  = sm + 52352;
    float* pcls  = sm + 52416;
    const uint32_t mbb = smem_u32(sm + 52736);
    const uint32_t mb_pz = mbb, mb_phh = mbb + 8, mb_cls = mbb + 16;

    const int tid = threadIdx.x;
    unsigned rank; asm("mov.u32 %0, %%cluster_ctarank;" : "=r"(rank));
    const int b0 = 2 * (blockIdx.x / CLUSTER);
    const int j0 = (int)rank * 32;
    const int w = tid >> 5, l = tid & 31;

    // transposed weight load: wT[g][kl][row] = W_g[row][512 + j0 + kl]
    for (int i = tid; i < 3 * 32 * 512; i += 512) {
        int g = i >> 14, rem = i & 16383, kl = rem >> 9, row = rem & 511;
        const float* W = (g == 0) ? Wz : (g == 1) ? Wr : Wh;
        wT[i] = W[(size_t)row * 1024 + 512 + j0 + kl];
    }
    if (tid < 64) hloc[tid] = 0.f;
    if (tid == 0) { mbar_init(mb_pz, 1); mbar_init(mb_phh, 1); mbar_init(mb_cls, 1); }
    __syncthreads();

    // push endpoints: warp w's partials all go to rank w
    const uint32_t pz_dst  = dsmem_map(smem_u32(&pz[rank * 128 + l * 4]), (unsigned)w);
    const uint32_t phh_dst = dsmem_map(smem_u32(&phh[rank * 64 + l * 2]), (unsigned)w);
    const uint32_t mpz_dst = dsmem_map(mb_pz, (unsigned)w);
    const uint32_t mph_dst = dsmem_map(mb_phh, (unsigned)w);

    cl_sync();                                    // mbars + weights + h0 live

    // gate-x prefetch (sum-thread roles)
    const int rl_zr = tid >> 2, bat_zr = tid & 1, gat_zr = (tid >> 1) & 1;
    const int rl_h = tid >> 1, bat_h = tid & 1;
    float gx_zr = 0.f, gx_h = 0.f;
    if (tid < 128)
        gx_zr = g_G[(size_t)(b0 + bat_zr) * 1536 + gat_zr * 512 + j0 + rl_zr];
    if (tid < 64)
        gx_h = g_G[(size_t)(b0 + bat_h) * 1536 + 1024 + j0 + rl_h];

    uint32_t ph = 0;
    for (int ts = 0; ts < S_LEN; ts++) {
        if (tid == 0) {
            mbar_expect_tx(mb_pz, 8192);           // 16 CTAs x 32 lanes x 16B
            mbar_expect_tx(mb_phh, 4096);          // 16 x 32 x 8B
        }
        const int tn = (ts + 1 < S_LEN) ? ts + 1 : ts;

        // ---- phase 1: z/r partials for global row = tid over local k-slice ----
        float zA = 0.f, zB = 0.f, rA = 0.f, rB = 0.f;
        {
            const float* wz = wT + tid;
            const float* wr = wT + 16384 + tid;
#pragma unroll
            for (int kl = 0; kl < 32; kl++) {
                float hA = hloc[kl], hB = hloc[32 + kl];
                float a = wz[kl * 512], b = wr[kl * 512];
                zA = fmaf(a, hA, zA); zB = fmaf(a, hB, zB);
                rA = fmaf(b, hA, rA); rB = fmaf(b, hB, rB);
            }
        }
        st_async128(pz_dst, mpz_dst, zA, zB, rA, rB);

        if (tid < 128) {                           // owners: sum + gate + r*h
            mbar_wait(mb_pz, ph);
            const float* p = pz + rl_zr * 4 + (tid & 3);
            float s0 = p[0]      + p[128]     + p[256]     + p[384];
            float s1 = p[512]    + p[640]     + p[768]     + p[896];
            float s2 = p[1024]   + p[1152]    + p[1280]    + p[1408];
            float s3 = p[1536]   + p[1664]    + p[1792]    + p[1920];
            float g = sigmoidf_((s0 + s1) + (s2 + s3) + gx_zr);
            if (gat_zr == 0) zloc[bat_zr * 32 + rl_zr] = g;
            else             rhloc[bat_zr * 32 + rl_zr] = g * hloc[bat_zr * 32 + rl_zr];
            gx_zr = g_G[((size_t)tn * 8 + b0 + bat_zr) * 1536 + gat_zr * 512 + j0 + rl_zr];
        }
        __syncthreads();                           // rhloc/zloc visible

        // ---- phase 2: h' partials over local r*h slice ----
        float hpA = 0.f, hpB = 0.f;
        {
            const float* wh = wT + 32768 + tid;
#pragma unroll
            for (int kl = 0; kl < 32; kl++) {
                float c = wh[kl * 512];
                hpA = fmaf(c, rhloc[kl], hpA);
                hpB = fmaf(c, rhloc[32 + kl], hpB);
            }
        }
        st_async64(phh_dst, mph_dst, hpA, hpB);

        if (tid < 64) {                            // owners: sum + tanh + h update
            mbar_wait(mb_phh, ph);
            const float* p = phh + rl_h * 2 + bat_h;
            float s0 = p[0]    + p[64]   + p[128]  + p[192];
            float s1 = p[256]  + p[320]  + p[384]  + p[448];
            float s2 = p[512]  + p[576]  + p[640]  + p[704];
            float s3 = p[768]  + p[832]  + p[896]  + p[960];
            float hc = tanh_fast((s0 + s1) + (s2 + s3) + gx_h);
            float hold = hloc[bat_h * 32 + rl_h];
            float z = zloc[bat_h * 32 + rl_h];
            hloc[bat_h * 32 + rl_h] = hold + z * (hc - hold);
            gx_h = g_G[((size_t)tn * 8 + b0 + bat_h) * 1536 + 1024 + j0 + rl_h];
        }
        __syncthreads();                           // hloc updated for next step
        ph ^= 1;
    }

    // ---- classifier: per-CTA partials over its 32 h rows -> gather at rank 0 --
    if (rank == 0 && tid == 0) mbar_expect_tx(mb_cls, 1280);  // 16 x 20 x 4B
    if (tid < 20) {
        int bat = tid / 10, cls = tid % 10;
        float s = 0.f;
        for (int r2 = 0; r2 < 32; r2++)
            s += hloc[bat * 32 + r2] * Wc[(size_t)cls * 512 + j0 + r2];
        uint32_t dst = dsmem_map(smem_u32(&pcls[rank * 20 + tid]), 0u);
        uint32_t mdst = dsmem_map(mb_cls, 0u);
        st_async32(dst, mdst, s);
    }
    if (rank == 0 && tid < 20) {
        mbar_wait(mb_cls, 0);
        int bat = tid / 10, cls = tid % 10;
        float s = 0.f;
#pragma unroll
        for (int src = 0; src < 16; src++) s += pcls[src * 20 + tid];
        out[(b0 + bat) * 10 + cls] = s;
    }
    cl_sync();                                     // no early-exit vs peer DSMEM
}

extern "C" void kernel_launch(void* const* d_in, const int* in_sizes, int n_in,
                              void* d_out, int out_size) {
    const float* x   = (const float*)d_in[0];
    const float* Wlm = (const float*)d_in[1];
    const float* Wz  = (const float*)d_in[2];
    const float* Wr  = (const float*)d_in[3];
    const float* Wh  = (const float*)d_in[4];
    const float* Wc  = (const float*)d_in[5];
    float* out = (float*)d_out;

    const int gemm_smem = 49152;
    const int gru_smem = 52736 * 4 + 32;           // ~211 KB < 227 KB
    cudaFuncSetAttribute(mma_gemm, cudaFuncAttributeMaxDynamicSharedMemorySize, gemm_smem);
    cudaFuncSetAttribute(gru_kernel, cudaFuncAttributeNonPortableClusterSizeAllowed, 1);
    cudaFuncSetAttribute(gru_kernel, cudaFuncAttributeMaxDynamicSharedMemorySize, gru_smem);

    __nv_bfloat16 *xh, *xl, *w1h, *w1l, *sh, *sl, *w2h, *w2l;
    float* G;
    cudaGetSymbolAddress((void**)&xh, g_xh);   cudaGetSymbolAddress((void**)&xl, g_xl);
    cudaGetSymbolAddress((void**)&w1h, g_w1h); cudaGetSymbolAddress((void**)&w1l, g_w1l);
    cudaGetSymbolAddress((void**)&sh, g_seqh); cudaGetSymbolAddress((void**)&sl, g_seql);
    cudaGetSymbolAddress((void**)&w2h, g_w2h); cudaGetSymbolAddress((void**)&w2l, g_w2l);
    cudaGetSymbolAddress((void**)&G, g_G);

    cvt_x<<<65536, 256>>>(x);
    cvt_w1<<<1024, 256>>>(Wlm);
    cvt_w2<<<768, 256>>>(Wz, Wr, Wh);
    mma_gemm<<<dim3(4, 256), 256, gemm_smem>>>(xh, xl, w1h, w1l,
                                               nullptr, sh, sl, DIN, DH);
    mma_gemm<<<dim3(12, 256), 256, gemm_smem>>>(sh, sl, w2h, w2l,
                                                G, nullptr, nullptr, DH, 3 * DH);
    gru_kernel<<<(BATCH / 2) * CLUSTER, 512, gru_smem>>>(Wz, Wr, Wh, Wc, out);
}

// round 16
// speedup vs baseline: 2.4650x; 1.1505x over previous
#include <cuda_runtime.h>
#include <cuda_bf16.h>
#include <cstdint>
#include <cstddef>

#define S_LEN 4096
#define BATCH 8
#define DH    512
#define DIN   2048
#define M_TOT (S_LEN * BATCH)
#define CLUSTER 16

// bf16 hi/lo operand arrays (GEMM phase, unchanged)
__device__ __nv_bfloat16 g_xh[(size_t)M_TOT * DIN], g_xl[(size_t)M_TOT * DIN];
__device__ __nv_bfloat16 g_w1h[DH * DIN], g_w1l[DH * DIN];
__device__ __nv_bfloat16 g_seqh[(size_t)M_TOT * DH], g_seql[(size_t)M_TOT * DH];
__device__ __nv_bfloat16 g_w2h[3 * DH * DH], g_w2l[3 * DH * DH];
__device__ float g_G[(size_t)M_TOT * 3 * DH];

__device__ __forceinline__ uint32_t pack_split2(float x, float y, uint32_t& lo) {
    __nv_bfloat16 hx = __float2bfloat16(x), hy = __float2bfloat16(y);
    __nv_bfloat16 lx = __float2bfloat16(x - __bfloat162float(hx));
    __nv_bfloat16 ly = __float2bfloat16(y - __bfloat162float(hy));
    lo = ((uint32_t)__bfloat16_as_ushort(ly) << 16) | __bfloat16_as_ushort(lx);
    return ((uint32_t)__bfloat16_as_ushort(hy) << 16) | __bfloat16_as_ushort(hx);
}
__device__ __forceinline__ void split_store4(float4 v, __nv_bfloat16* ph, __nv_bfloat16* pl) {
    uint2 h, l;
    h.x = pack_split2(v.x, v.y, l.x);
    h.y = pack_split2(v.z, v.w, l.y);
    *reinterpret_cast<uint2*>(ph) = h;
    *reinterpret_cast<uint2*>(pl) = l;
}

__global__ __launch_bounds__(256) void cvt_x(const float* __restrict__ x) {
    size_t i4 = (size_t)blockIdx.x * 256 + threadIdx.x;
    int m = (int)(i4 >> 9), kq = (int)(i4 & 511);
    int b = m & 7, t = m >> 3;
    float4 v = reinterpret_cast<const float4*>(x)[((size_t)b * S_LEN + t) * 512 + kq];
    size_t o = (size_t)m * DIN + kq * 4;
    split_store4(v, g_xh + o, g_xl + o);
}
__global__ __launch_bounds__(256) void cvt_w1(const float* __restrict__ Wlm) {
    int i4 = blockIdx.x * 256 + threadIdx.x;
    float4 v = reinterpret_cast<const float4*>(Wlm)[i4];
    size_t o = (size_t)i4 * 4;
    split_store4(v, g_w1h + o, g_w1l + o);
}
__global__ __launch_bounds__(256) void cvt_w2(const float* __restrict__ Wz,
                                              const float* __restrict__ Wr,
                                              const float* __restrict__ Wh) {
    int i4 = blockIdx.x * 256 + threadIdx.x;
    int n = i4 >> 7, kq = i4 & 127;
    const float* W = (n < 512) ? Wz : (n < 1024) ? Wr : Wh;
    float4 v = reinterpret_cast<const float4*>(W + (size_t)(n & 511) * 1024)[kq];
    size_t o = (size_t)n * DH + kq * 4;
    split_store4(v, g_w2h + o, g_w2l + o);
}

// ---------------- bf16x3 tensor-core GEMM (unchanged) ----------------
__device__ __forceinline__ void cp16(uint32_t dst, const void* src) {
    asm volatile("cp.async.cg.shared.global [%0], [%1], 16;" :: "r"(dst), "l"(src));
}
#define MMA_BF16(c, a0, a1, a2, a3, b0, b1) \
    asm volatile("mma.sync.aligned.m16n8k16.row.col.f32.bf16.bf16.f32 " \
        "{%0,%1,%2,%3}, {%4,%5,%6,%7}, {%8,%9}, {%0,%1,%2,%3};" \
        : "+f"((c)[0]), "+f"((c)[1]), "+f"((c)[2]), "+f"((c)[3]) \
        : "r"(a0), "r"(a1), "r"(a2), "r"(a3), "r"(b0), "r"(b1))

__global__ __launch_bounds__(256) void mma_gemm(
    const __nv_bfloat16* __restrict__ Ah, const __nv_bfloat16* __restrict__ Al,
    const __nv_bfloat16* __restrict__ Bh, const __nv_bfloat16* __restrict__ Bl,
    float* __restrict__ Cf, __nv_bfloat16* __restrict__ Ch, __nv_bfloat16* __restrict__ Cl,
    int K, int N)
{
    extern __shared__ uint32_t sw[];
    const int tid = threadIdx.x;
    const int m0 = blockIdx.y * 128, n0 = blockIdx.x * 128;
    const int w = tid >> 5, l = tid & 31;
    const int wm = (w >> 2) * 64, wn = (w & 3) * 32;
    const int lq = l >> 2, lr = l & 3;
    const int row = tid >> 1, half = tid & 1;
    const uint32_t sbase = (uint32_t)__cvta_generic_to_shared(sw);
    const int NK = K >> 4;

    float acc[4][4][4];
#pragma unroll
    for (int a = 0; a < 4; a++)
#pragma unroll
        for (int b = 0; b < 4; b++)
#pragma unroll
            for (int c = 0; c < 4; c++) acc[a][b][c] = 0.f;

    const size_t arow = (size_t)(m0 + row) * K + half * 8;
    const size_t brow = (size_t)(n0 + row) * K + half * 8;
    {
        uint32_t d = sbase + (row * 12 + half * 4) * 4;
        cp16(d,         Ah + arow);
        cp16(d + 6144,  Al + arow);
        cp16(d + 12288, Bh + brow);
        cp16(d + 18432, Bl + brow);
        asm volatile("cp.async.commit_group;" ::: "memory");
    }
    for (int i = 0; i < NK; i++) {
        asm volatile("cp.async.wait_group 0;" ::: "memory");
        __syncthreads();
        const int st = i & 1;
        if (i + 1 < NK) {
            const int k0 = (i + 1) << 4;
            uint32_t d = sbase + ((st ^ 1) * 6144 + row * 12 + half * 4) * 4;
            cp16(d,         Ah + arow + k0);
            cp16(d + 6144,  Al + arow + k0);
            cp16(d + 12288, Bh + brow + k0);
            cp16(d + 18432, Bl + brow + k0);
            asm volatile("cp.async.commit_group;" ::: "memory");
        }
        const uint32_t* S = sw + st * 6144;
        uint32_t bh0[4], bh1[4], bl0[4], bl1[4];
#pragma unroll
        for (int nt = 0; nt < 4; nt++) {
            int o = 3072 + (wn + nt * 8 + lq) * 12 + lr;
            bh0[nt] = S[o]; bh1[nt] = S[o + 4];
            bl0[nt] = S[o + 1536]; bl1[nt] = S[o + 1540];
        }
#pragma unroll
        for (int mt = 0; mt < 4; mt++) {
            int m = wm + mt * 16 + lq;
            int o1 = m * 12 + lr, o2 = (m + 8) * 12 + lr;
            uint32_t ah0 = S[o1], ah1 = S[o2], ah2 = S[o1 + 4], ah3 = S[o2 + 4];
            uint32_t al0 = S[o1 + 1536], al1 = S[o2 + 1536];
            uint32_t al2 = S[o1 + 1540], al3 = S[o2 + 1540];
#pragma unroll
            for (int nt = 0; nt < 4; nt++) {
                MMA_BF16(acc[mt][nt], ah0, ah1, ah2, ah3, bh0[nt], bh1[nt]);
                MMA_BF16(acc[mt][nt], ah0, ah1, ah2, ah3, bl0[nt], bl1[nt]);
                MMA_BF16(acc[mt][nt], al0, al1, al2, al3, bh0[nt], bh1[nt]);
            }
        }
    }
#pragma unroll
    for (int mt = 0; mt < 4; mt++) {
#pragma unroll
        for (int nt = 0; nt < 4; nt++) {
            int m = m0 + wm + mt * 16 + lq;
            int c = n0 + wn + nt * 8 + lr * 2;
            const float* a = acc[mt][nt];
            if (Cf) {
                *reinterpret_cast<float2*>(Cf + (size_t)m * N + c)       = make_float2(a[0], a[1]);
                *reinterpret_cast<float2*>(Cf + (size_t)(m + 8) * N + c) = make_float2(a[2], a[3]);
            } else {
                uint32_t lo0, lo1;
                uint32_t hi0 = pack_split2(a[0], a[1], lo0);
                uint32_t hi1 = pack_split2(a[2], a[3], lo1);
                *reinterpret_cast<uint32_t*>(Ch + (size_t)m * N + c)       = hi0;
                *reinterpret_cast<uint32_t*>(Cl + (size_t)m * N + c)       = lo0;
                *reinterpret_cast<uint32_t*>(Ch + (size_t)(m + 8) * N + c) = hi1;
                *reinterpret_cast<uint32_t*>(Cl + (size_t)(m + 8) * N + c) = lo1;
            }
        }
    }
}

// ================= cluster / mbarrier / f32x2 helpers =================
__device__ __forceinline__ uint32_t smem_u32(const void* p) {
    return (uint32_t)__cvta_generic_to_shared(p);
}
__device__ __forceinline__ uint32_t dsmem_map(uint32_t a, unsigned r) {
    uint32_t x; asm("mapa.shared::cluster.u32 %0, %1, %2;" : "=r"(x) : "r"(a), "r"(r)); return x;
}
__device__ __forceinline__ void st_async32(uint32_t a, uint32_t mbar, float x) {
    asm volatile("st.async.shared::cluster.mbarrier::complete_tx::bytes.b32 [%0], %1, [%2];"
                 :: "r"(a), "r"(__float_as_uint(x)), "r"(mbar) : "memory");
}
__device__ __forceinline__ void st_async_u64(uint32_t a, uint32_t mbar, unsigned long long v) {
    asm volatile("st.async.shared::cluster.mbarrier::complete_tx::bytes.u64 [%0], %1, [%2];"
                 :: "r"(a), "l"(v), "r"(mbar) : "memory");
}
__device__ __forceinline__ void mbar_init(uint32_t a, uint32_t cnt) {
    asm volatile("mbarrier.init.shared.b64 [%0], %1;" :: "r"(a), "r"(cnt) : "memory");
}
__device__ __forceinline__ void mbar_expect_tx(uint32_t a, uint32_t tx) {
    asm volatile("mbarrier.arrive.expect_tx.shared.b64 _, [%0], %1;" :: "r"(a), "r"(tx) : "memory");
}
__device__ __forceinline__ void mbar_wait(uint32_t a, uint32_t parity) {
    uint32_t done;
    asm volatile("{\n\t.reg .pred p;\n\t"
                 "mbarrier.try_wait.parity.shared.b64 p, [%1], %2, 0x989680;\n\t"
                 "selp.b32 %0, 1, 0, p;\n\t}"
                 : "=r"(done) : "r"(a), "r"(parity) : "memory");
    while (!done) {
        asm volatile("{\n\t.reg .pred p;\n\t"
                     "mbarrier.try_wait.parity.shared.b64 p, [%1], %2, 0x989680;\n\t"
                     "selp.b32 %0, 1, 0, p;\n\t}"
                     : "=r"(done) : "r"(a), "r"(parity) : "memory");
    }
}
__device__ __forceinline__ void cl_sync() {
    asm volatile("barrier.cluster.arrive.aligned;" ::: "memory");
    asm volatile("barrier.cluster.wait.aligned;"   ::: "memory");
}
__device__ __forceinline__ float sigmoidf_(float v) { return 1.f / (1.f + __expf(-v)); }
__device__ __forceinline__ float tanh_fast(float v) {
    float y; asm("tanh.approx.f32 %0, %1;" : "=f"(y) : "f"(v)); return y;
}
__device__ __forceinline__ unsigned long long f2pack(float x, float y) {
    unsigned long long r; asm("mov.b64 %0, {%1,%2};" : "=l"(r) : "f"(x), "f"(y)); return r;
}
__device__ __forceinline__ void f2unpack(unsigned long long v, float& x, float& y) {
    asm("mov.b64 {%0,%1}, %2;" : "=f"(x), "=f"(y) : "l"(v));
}
__device__ __forceinline__ void fma2(unsigned long long& a, unsigned long long b,
                                     unsigned long long c) {
    asm("fma.rn.f32x2 %0, %1, %2, %0;" : "+l"(a) : "l"(b), "l"(c));
}
__device__ __forceinline__ void add2(unsigned long long& a, unsigned long long b) {
    asm("add.rn.f32x2 %0, %1, %2;" : "=l"(a) : "l"(a), "l"(b));
}

// ==== k-sliced GRU v2: staggered batches, z/r weights packed in registers ======
// CTA rank c owns h rows [32c,32c+32) and k-slice [32c,32c+32). Thread tid owns
// global row tid: wzr[kl] = packed {Wz[tid][...], Wr[tid][...]} in 64 registers.
// Step: p1(A) push -> p1(B) push (covers A flight) -> warp0 sums A / warp1 sums
// B concurrently -> sync -> merged p2 (wh read once) push pairs -> warp0/1
// update hA/hB -> sync.  phh/pz single-buffered (safety chain as R14).
// smem floats: whT[32][512]@0 | pz[2][16][32][2]@16384 | phh[16][32][2]@18432
//   hloc[2][32]@19456 | rhloc[32][2]@19520 | pcls[16][20]@19584 | mbars@19904
__global__ void __cluster_dims__(CLUSTER, 1, 1) __launch_bounds__(512, 1)
gru_kernel(const float* __restrict__ Wz, const float* __restrict__ Wr,
           const float* __restrict__ Wh, const float* __restrict__ Wc,
           float* __restrict__ out) {
    extern __shared__ float sm[];
    float* whT   = sm;
    float* pz    = sm + 16384;
    float* phh   = sm + 18432;
    float* hloc  = sm + 19456;
    float* rhloc = sm + 19520;
    float* pcls  = sm + 19584;
    const uint32_t mbb = smem_u32(sm + 19904);
    const uint32_t mb_pzA = mbb, mb_pzB = mbb + 8, mb_ph = mbb + 16, mb_cls = mbb + 24;

    const int tid = threadIdx.x;
    unsigned rank; asm("mov.u32 %0, %%cluster_ctarank;" : "=r"(rank));
    const int b0 = 2 * (blockIdx.x / CLUSTER);
    const int j0 = (int)rank * 32;
    const int w = tid >> 5, l = tid & 31;

    // wh (phase-2) weights smem-transposed: whT[kl*512 + row]
    for (int i = tid; i < 16384; i += 512) {
        int kl = i >> 9, row = i & 511;
        whT[i] = Wh[(size_t)row * 1024 + 512 + j0 + kl];
    }
    // z/r weights register-resident, packed {wz, wr} per k (row = tid)
    unsigned long long wzr[32];
#pragma unroll
    for (int kl = 0; kl < 32; kl++) {
        float wzv = Wz[(size_t)tid * 1024 + 512 + j0 + kl];
        float wrv = Wr[(size_t)tid * 1024 + 512 + j0 + kl];
        wzr[kl] = f2pack(wzv, wrv);
    }
    if (tid < 64) hloc[tid] = 0.f;
    if (tid == 0) {
        mbar_init(mb_pzA, 1); mbar_init(mb_pzB, 1);
        mbar_init(mb_ph, 1);  mbar_init(mb_cls, 1);
    }
    __syncthreads();

    // push endpoints (dest rank = w; slot = my rank, local row l)
    const uint32_t pzA_dst = dsmem_map(smem_u32(&pz[((0 * 16 + (int)rank) * 32 + l) * 2]), (unsigned)w);
    const uint32_t pzB_dst = dsmem_map(smem_u32(&pz[((1 * 16 + (int)rank) * 32 + l) * 2]), (unsigned)w);
    const uint32_t ph_dst  = dsmem_map(smem_u32(&phh[((int)rank * 32 + l) * 2]), (unsigned)w);
    const uint32_t mpzA_r = dsmem_map(mb_pzA, (unsigned)w);
    const uint32_t mpzB_r = dsmem_map(mb_pzB, (unsigned)w);
    const uint32_t mph_r  = dsmem_map(mb_ph, (unsigned)w);

    cl_sync();                                     // mbars + weights + h0 live

    // owner prefetch: warp0 = batch A, warp1 = batch B (lane l = local row)
    float gxz = 0.f, gxr = 0.f, gxh = 0.f, zown = 0.f;
    if (w < 2) {
        const size_t gb = (size_t)(b0 + w) * 1536;
        gxz = g_G[gb + j0 + l];
        gxr = g_G[gb + 512 + j0 + l];
        gxh = g_G[gb + 1024 + j0 + l];
    }

    uint32_t phs = 0;
    for (int t = 0; t < S_LEN; t++) {
        if (tid == 0) {
            mbar_expect_tx(mb_pzA, 4096);          // 16 src x 32 rows x 8B
            mbar_expect_tx(mb_pzB, 4096);
            mbar_expect_tx(mb_ph, 4096);           // pairs {hpA,hpB}
        }
        const int tn = (t + 1 < S_LEN) ? t + 1 : t;

        // ---- phase 1, batch A: packed {z,r} partial; push early ----
        unsigned long long accA = 0ULL;
#pragma unroll
        for (int kl = 0; kl < 32; kl++) {
            float h = hloc[kl];
            fma2(accA, wzr[kl], f2pack(h, h));
        }
        st_async_u64(pzA_dst, mpzA_r, accA);

        // ---- phase 1, batch B (covers A's flight) ----
        unsigned long long accB = 0ULL;
#pragma unroll
        for (int kl = 0; kl < 32; kl++) {
            float h = hloc[32 + kl];
            fma2(accB, wzr[kl], f2pack(h, h));
        }
        st_async_u64(pzB_dst, mpzB_r, accB);

        // ---- owner reductions: warp0 (A) and warp1 (B) concurrently ----
        if (w < 2) {
            mbar_wait(w ? mb_pzB : mb_pzA, phs);
            unsigned long long s = 0ULL;
#pragma unroll
            for (int src = 0; src < 16; src++)
                add2(s, *(const unsigned long long*)&pz[((w * 16 + src) * 32 + l) * 2]);
            float zs, rs; f2unpack(s, zs, rs);
            zown = sigmoidf_(zs + gxz);
            float r = sigmoidf_(rs + gxr);
            rhloc[l * 2 + w] = r * hloc[w * 32 + l];
            const size_t gbn = ((size_t)tn * 8 + b0 + w) * 1536;
            gxz = g_G[gbn + j0 + l];
            gxr = g_G[gbn + 512 + j0 + l];
        }
        __syncthreads();                           // rhloc ready

        // ---- merged phase 2: both batches, wh read once ----
        unsigned long long accH = 0ULL;
#pragma unroll
        for (int kl = 0; kl < 32; kl++) {
            unsigned long long rh2 = *(const unsigned long long*)&rhloc[kl * 2];
            float whv = whT[kl * 512 + tid];
            fma2(accH, f2pack(whv, whv), rh2);
        }
        st_async_u64(ph_dst, mph_r, accH);

        if (w < 2) {                               // h update (A on w0, B on w1)
            mbar_wait(mb_ph, phs);
            float s = 0.f;
#pragma unroll
            for (int src = 0; src < 16; src++)
                s += phh[(src * 32 + l) * 2 + w];
            float hc = tanh_fast(s + gxh);
            float hold = hloc[w * 32 + l];
            hloc[w * 32 + l] = hold + zown * (hc - hold);
            gxh = g_G[((size_t)tn * 8 + b0 + w) * 1536 + 1024 + j0 + l];
        }
        __syncthreads();                           // hloc updated
        phs ^= 1;
    }

    // ---- classifier: per-CTA partials -> gather at rank 0 ----
    if (rank == 0 && tid == 0) mbar_expect_tx(mb_cls, 1280);
    if (tid < 20) {
        int bat = tid / 10, cls = tid % 10;
        float s = 0.f;
        for (int r2 = 0; r2 < 32; r2++)
            s += hloc[bat * 32 + r2] * Wc[(size_t)cls * 512 + j0 + r2];
        uint32_t dst = dsmem_map(smem_u32(&pcls[rank * 20 + tid]), 0u);
        uint32_t mdst = dsmem_map(mb_cls, 0u);
        st_async32(dst, mdst, s);
    }
    if (rank == 0 && tid < 20) {
        mbar_wait(mb_cls, 0);
        int bat = tid / 10, cls = tid % 10;
        float s = 0.f;
#pragma unroll
        for (int src = 0; src < 16; src++) s += pcls[src * 20 + tid];
        out[(b0 + bat) * 10 + cls] = s;
    }
    cl_sync();                                     // no early-exit vs peer DSMEM
}

extern "C" void kernel_launch(void* const* d_in, const int* in_sizes, int n_in,
                              void* d_out, int out_size) {
    const float* x   = (const float*)d_in[0];
    const float* Wlm = (const float*)d_in[1];
    const float* Wz  = (const float*)d_in[2];
    const float* Wr  = (const float*)d_in[3];
    const float* Wh  = (const float*)d_in[4];
    const float* Wc  = (const float*)d_in[5];
    float* out = (float*)d_out;

    const int gemm_smem = 49152;
    const int gru_smem = 19912 * 4 + 32;           // ~80 KB
    cudaFuncSetAttribute(mma_gemm, cudaFuncAttributeMaxDynamicSharedMemorySize, gemm_smem);
    cudaFuncSetAttribute(gru_kernel, cudaFuncAttributeNonPortableClusterSizeAllowed, 1);
    cudaFuncSetAttribute(gru_kernel, cudaFuncAttributeMaxDynamicSharedMemorySize, gru_smem);

    __nv_bfloat16 *xh, *xl, *w1h, *w1l, *sh, *sl, *w2h, *w2l;
    float* G;
    cudaGetSymbolAddress((void**)&xh, g_xh);   cudaGetSymbolAddress((void**)&xl, g_xl);
    cudaGetSymbolAddress((void**)&w1h, g_w1h); cudaGetSymbolAddress((void**)&w1l, g_w1l);
    cudaGetSymbolAddress((void**)&sh, g_seqh); cudaGetSymbolAddress((void**)&sl, g_seql);
    cudaGetSymbolAddress((void**)&w2h, g_w2h); cudaGetSymbolAddress((void**)&w2l, g_w2l);
    cudaGetSymbolAddress((void**)&G, g_G);

    cvt_x<<<65536, 256>>>(x);
    cvt_w1<<<1024, 256>>>(Wlm);
    cvt_w2<<<768, 256>>>(Wz, Wr, Wh);
    mma_gemm<<<dim3(4, 256), 256, gemm_smem>>>(xh, xl, w1h, w1l,
                                               nullptr, sh, sl, DIN, DH);
    mma_gemm<<<dim3(12, 256), 256, gemm_smem>>>(sh, sl, w2h, w2l,
                                                G, nullptr, nullptr, DH, 3 * DH);
    gru_kernel<<<(BATCH / 2) * CLUSTER, 512, gru_smem>>>(Wz, Wr, Wh, Wc, out);
}